// round 12
// baseline (speedup 1.0000x reference)
#include <cuda_runtime.h>
#include <cstdint>

// Problem constants
#define BB   2
#define SS   2048
#define TT   2048
#define CHN  1024
#define NH   16
#define HD   64
#define MM   (BB * SS)   // 4096 rows

// Scratch (device globals: allocation-free rule)
__device__ float g_Q[(size_t)MM * CHN];
__device__ float g_K[(size_t)MM * CHN];
__device__ float g_V[(size_t)MM * CHN];
__device__ float g_A[(size_t)MM * CHN];

// ---------------- helpers ----------------
__device__ __forceinline__ uint32_t f2tf(float x) {
    uint32_t u;
    asm("cvt.rna.tf32.f32 %0, %1;\n" : "=r"(u) : "f"(x));
    return u;
}
__device__ __forceinline__ float f2tf_f(float x) {
    return __uint_as_float(f2tf(x));
}
__device__ __forceinline__ uint32_t fu(float x) { return __float_as_uint(x); }

__device__ __forceinline__ float4 tf4(float4 v) {
    return make_float4(f2tf_f(v.x), f2tf_f(v.y), f2tf_f(v.z), f2tf_f(v.w));
}

__device__ __forceinline__ uint32_t smem_u32(const void* p) {
    return (uint32_t)__cvta_generic_to_shared(p);
}

// D(16x8) += A(16x8, tf32, row) * B(8x8, tf32, col)
__device__ __forceinline__ void mma8(float c[4], const uint32_t a[4], const uint32_t b[2]) {
    asm volatile(
        "mma.sync.aligned.m16n8k8.row.col.f32.tf32.tf32.f32 "
        "{%0,%1,%2,%3}, {%4,%5,%6,%7}, {%8,%9}, {%0,%1,%2,%3};\n"
        : "+f"(c[0]), "+f"(c[1]), "+f"(c[2]), "+f"(c[3])
        : "r"(a[0]), "r"(a[1]), "r"(a[2]), "r"(a[3]), "r"(b[0]), "r"(b[1]));
}

// ldmatrix x4: 4 8x8-b16 matrices (= 8x4-tf32 blocks); exact tf32 frag layout.
__device__ __forceinline__ void ldsm_x4(uint32_t r[4], uint32_t saddr) {
    asm volatile("ldmatrix.sync.aligned.m8n8.x4.shared.b16 {%0,%1,%2,%3}, [%4];"
        : "=r"(r[0]), "=r"(r[1]), "=r"(r[2]), "=r"(r[3]) : "r"(saddr));
}

// ---------------- GEMM body (R9-proven): C[4096,1024] = X @ W + bias ----------------
// BM=128, BN=128, BK=32, 256 threads (8 warps = 4m x 2n), LDSM fragments,
// double-buffered smem + register prefetch.
// ROUND_OUT: round result to tf32 at store (for Q/K/V so flash skips cvt;
// f2tf is idempotent -> downstream values bit-identical). Final out: false.
#define GXF   (128 * 36)
#define GWF   (128 * 36)
#define GSTG  (GXF + GWF)
#define GSTGB (GSTG * 4)

template <bool ROUND_OUT>
__device__ __forceinline__ void gemm_body(
    const float* __restrict__ X, const float* __restrict__ W,
    const float* __restrict__ bias, float* __restrict__ C,
    const float* __restrict__ maskScale, float* gsm)
{
    const uint32_t gsb = smem_u32(gsm);

    const int tid  = threadIdx.x;
    const int lane = tid & 31;
    const int warp = tid >> 5;
    const int g    = lane >> 2;
    const int tg   = lane & 3;
    const int wm   = warp >> 1;   // 0..3
    const int wn   = warp & 1;    // 0..1
    const int m0   = blockIdx.y * 128;
    const int n0   = blockIdx.x * 128;

    const uint32_t a_thr = (uint32_t)(((wm * 32 + (lane & 15)) * 36 + (lane >> 4) * 4) * 4);
    const uint32_t b_thr = (uint32_t)(((wn * 64 + ((lane >> 4) * 8) + (lane & 7)) * 36
                                      + (((lane >> 3) & 1) * 4)) * 4);

    float4 px[4], pw[4];

    auto ldg_tile = [&](int kt) {
#pragma unroll
        for (int i = 0; i < 4; i++) {
            int idx = i * 256 + tid;
            int xr = idx >> 3, xc = (idx & 7) * 4;
            px[i] = *(const float4*)&X[(size_t)(m0 + xr) * 1024 + kt + xc];
        }
        const int bn = tid & 127;
        const int bh = tid >> 7;
#pragma unroll
        for (int j = 0; j < 4; j++) {
            int kq = bh * 4 + j;
            pw[j] = make_float4(
                W[(size_t)(kt + kq * 4 + 0) * 1024 + n0 + bn],
                W[(size_t)(kt + kq * 4 + 1) * 1024 + n0 + bn],
                W[(size_t)(kt + kq * 4 + 2) * 1024 + n0 + bn],
                W[(size_t)(kt + kq * 4 + 3) * 1024 + n0 + bn]);
        }
    };
    auto sts_tile = [&](int st) {
        float* Xs = gsm + st * GSTG;
        float* Ws = Xs + GXF;
#pragma unroll
        for (int i = 0; i < 4; i++) {
            int idx = i * 256 + tid;
            int xr = idx >> 3, xc = (idx & 7) * 4;
            *(float4*)&Xs[xr * 36 + xc] = tf4(px[i]);
        }
        const int bn = tid & 127;
        const int bh = tid >> 7;
#pragma unroll
        for (int j = 0; j < 4; j++) {
            int kq = bh * 4 + j;
            *(float4*)&Ws[bn * 36 + kq * 4] = tf4(pw[j]);
        }
    };

    float c[2][8][4];
#pragma unroll
    for (int mt = 0; mt < 2; mt++)
#pragma unroll
        for (int nt = 0; nt < 8; nt++)
#pragma unroll
            for (int e = 0; e < 4; e++) c[mt][nt][e] = 0.f;

    ldg_tile(0);
    sts_tile(0);
    __syncthreads();

    for (int kt = 0; kt < 32; kt++) {
        if (kt + 1 < 32) ldg_tile((kt + 1) * 32);

        const uint32_t xa = gsb + (kt & 1) * GSTGB + a_thr;
        const uint32_t wa = gsb + (kt & 1) * GSTGB + GXF * 4 + b_thr;

#pragma unroll
        for (int kk = 0; kk < 4; kk++) {
            uint32_t af[2][4], bf[4][4];
            ldsm_x4(af[0], xa + kk * 32);
            ldsm_x4(af[1], xa + 16 * 36 * 4 + kk * 32);
#pragma unroll
            for (int p = 0; p < 4; p++)
                ldsm_x4(bf[p], wa + p * (16 * 36 * 4) + kk * 32);
#pragma unroll
            for (int p = 0; p < 4; p++) {
                mma8(c[0][2 * p],     af[0], &bf[p][0]);
                mma8(c[0][2 * p + 1], af[0], &bf[p][2]);
                mma8(c[1][2 * p],     af[1], &bf[p][0]);
                mma8(c[1][2 * p + 1], af[1], &bf[p][2]);
            }
        }

        if (kt + 1 < 32) sts_tile((kt + 1) & 1);
        __syncthreads();
    }

#pragma unroll
    for (int mt = 0; mt < 2; mt++) {
        int r0 = m0 + wm * 32 + mt * 16 + g;
        int r1 = r0 + 8;
        float sc0 = 1.f, sc1 = 1.f;
        if (maskScale) {
            sc0 = maskScale[(size_t)r0 * TT];
            sc1 = maskScale[(size_t)r1 * TT];
        }
#pragma unroll
        for (int nt = 0; nt < 8; nt++) {
            int col = n0 + wn * 64 + nt * 8 + 2 * tg;
            float b0 = bias[col], b1 = bias[col + 1];
            float v00 = (c[mt][nt][0] + b0) * sc0;
            float v01 = (c[mt][nt][1] + b1) * sc0;
            float v10 = (c[mt][nt][2] + b0) * sc1;
            float v11 = (c[mt][nt][3] + b1) * sc1;
            if (ROUND_OUT) {
                v00 = f2tf_f(v00); v01 = f2tf_f(v01);
                v10 = f2tf_f(v10); v11 = f2tf_f(v11);
            }
            *(float2*)&C[(size_t)r0 * 1024 + col] = make_float2(v00, v01);
            *(float2*)&C[(size_t)r1 * 1024 + col] = make_float2(v10, v11);
        }
    }
}

// Fused QKV projections: blockIdx.z picks (input, weight, bias, output)
__global__ void __launch_bounds__(256, 2) qkv_gemm_kernel(
    const float* __restrict__ query, const float* __restrict__ key,
    const float* __restrict__ value,
    const float* __restrict__ Wq, const float* __restrict__ Wk,
    const float* __restrict__ Wv,
    const float* __restrict__ bq, const float* __restrict__ bk,
    const float* __restrict__ bv,
    float* __restrict__ Qp, float* __restrict__ Kp, float* __restrict__ Vp)
{
    extern __shared__ float gsm[];
    const int z = blockIdx.z;   // uniform per CTA
    const float* X    = (z == 0) ? query : (z == 1) ? key : value;
    const float* W    = (z == 0) ? Wq    : (z == 1) ? Wk  : Wv;
    const float* bias = (z == 0) ? bq    : (z == 1) ? bk  : bv;
    float*       C    = (z == 0) ? Qp    : (z == 1) ? Kp  : Vp;
    gemm_body<true>(X, W, bias, C, nullptr, gsm);   // tf32-rounded outputs
}

// Output projection (with mask scaling); final answer stays full fp32.
__global__ void __launch_bounds__(256, 2) out_gemm_kernel(
    const float* __restrict__ X, const float* __restrict__ W,
    const float* __restrict__ bias, float* __restrict__ C,
    const float* __restrict__ maskScale)
{
    extern __shared__ float gsm[];
    gemm_body<false>(X, W, bias, C, maskScale, gsm);
}

// ---------------- Flash attention v6: 128-t fill, 2x 64-t compute ----------------
// Grid: (S/128, H, B). 128 threads = 4 warps; warp owns 2 m-tiles (R9 pipeline).
// K/V fill covers 128 t-rows per barrier pair; inner pipeline runs twice
// (halves barrier count + fill-latency exposures, registers unchanged).
// Inputs g_Q/g_K/g_V are pre-rounded tf32 -> fills are straight copies.
// Ks: [t][d] 128x68. Vs: [d][t] 64x132 (transposed fill).
#define LDS_  68
#define VST   132
#define FCH2  128
#define NCH2  (TT / FCH2)   // 16 big chunks
#define FSMEM_F (128 * LDS_ + 128 * LDS_ + 64 * VST)   // 25,856 floats

__global__ void __launch_bounds__(128) flash_attn_kernel(
    const float* __restrict__ mask, const int* __restrict__ causal_p)
{
    extern __shared__ float sm[];
    float* Qs = sm;                      // 128 x 68 (P reuses own rows)
    float* Ks = sm + 128 * LDS_;         // 128 x 68  [t][d]
    float* Vs = sm + 256 * LDS_;         // 64 x 132  [d][t]

    const int tid  = threadIdx.x;
    const int lane = tid & 31;
    const int warp = tid >> 5;
    const int g    = lane >> 2;
    const int tg   = lane & 3;
    const int s0   = blockIdx.x * 128;
    const int h    = blockIdx.y;
    const int b    = blockIdx.z;
    const int causal = causal_p[0];

    const uint32_t Qs_u = smem_u32(Qs);
    const uint32_t Ks_u = smem_u32(Ks);
    const uint32_t Vs_u = smem_u32(Vs);

    const uint32_t bK = Ks_u + (uint32_t)(((((lane >> 4) * 8) + (lane & 7)) * LDS_
                                           + (((lane >> 3) & 1) * 4)) * 4);
    const uint32_t bV = Vs_u + (uint32_t)(((((lane >> 4) * 8) + (lane & 7)) * VST
                                           + (((lane >> 3) & 1) * 4)) * 4);
    const uint32_t aP0 = Qs_u + (uint32_t)(((warp * 32 + (lane & 15)) * LDS_
                                            + ((lane >> 4) * 4)) * 4);
    const uint32_t aP1 = aP0 + (uint32_t)(16 * LDS_ * 4);

    // Load Q tile [128 x 64] (already tf32-rounded by projection GEMM)
    const size_t qoff = ((size_t)b * SS + s0) * CHN + h * HD;
#pragma unroll
    for (int i = 0; i < 16; i++) {
        int idx = i * 128 + tid;
        int r = idx >> 4, cc = (idx & 15) * 4;
        *(float4*)&Qs[r * LDS_ + cc] = *(const float4*)&g_Q[qoff + (size_t)r * CHN + cc];
    }
    __syncthreads();

    uint32_t qa[2][8][4];
#pragma unroll
    for (int mt = 0; mt < 2; mt++) {
        uint32_t base = (mt == 0) ? aP0 : aP1;
#pragma unroll
        for (int j = 0; j < 8; j++) ldsm_x4(qa[mt][j], base + j * 32);
    }

    float o[2][8][4];
#pragma unroll
    for (int mt = 0; mt < 2; mt++)
#pragma unroll
        for (int nt = 0; nt < 8; nt++)
#pragma unroll
            for (int e = 0; e < 4; e++) o[mt][nt][e] = 0.f;
    float mr[2][2] = {{-1e30f, -1e30f}, {-1e30f, -1e30f}};
    float lr[2][2] = {{0.f, 0.f}, {0.f, 0.f}};

    const float* mb = mask + (size_t)b * SS * TT;
    const int vd  = tid & 63;
    const int vth = tid >> 6;   // 0/1: t-half for V fill

    for (int ic = 0; ic < NCH2; ic++) {
        __syncthreads();   // all warps done reading previous K/V

        const size_t kvoff = ((size_t)b * TT + ic * FCH2) * CHN + h * HD;
        // K fill [128t x 64d]: 2048 float4 / 128 thr (pre-rounded, copy only)
#pragma unroll
        for (int i = 0; i < 16; i++) {
            int idx = i * 128 + tid;
            int r = idx >> 4, cc = (idx & 15) * 4;
            *(float4*)&Ks[r * LDS_ + cc] =
                *(const float4*)&g_K[kvoff + (size_t)r * CHN + cc];
        }
        // V fill transposed [64d x 128t]: thread owns d=vd, 16 t-quads
#pragma unroll
        for (int q16 = 0; q16 < 16; q16++) {
            int q = vth * 16 + q16;   // t-quad 0..31
            float4 vv = make_float4(
                g_V[kvoff + (size_t)(q * 4 + 0) * CHN + vd],
                g_V[kvoff + (size_t)(q * 4 + 1) * CHN + vd],
                g_V[kvoff + (size_t)(q * 4 + 2) * CHN + vd],
                g_V[kvoff + (size_t)(q * 4 + 3) * CHN + vd]);
            *(float4*)&Vs[vd * VST + q * 4] = vv;
        }
        __syncthreads();

#pragma unroll
        for (int half = 0; half < 2; half++) {
            const int t0 = ic * FCH2 + half * 64;
            const uint32_t bKh = bK + (uint32_t)(half * 64 * LDS_ * 4);
            const uint32_t bVh = bV + (uint32_t)(half * 64 * 4);

            // S = Q K^T
            float s[2][8][4];
#pragma unroll
            for (int mt = 0; mt < 2; mt++)
#pragma unroll
                for (int nt = 0; nt < 8; nt++)
#pragma unroll
                    for (int e = 0; e < 4; e++) s[mt][nt][e] = 0.f;
#pragma unroll
            for (int ks = 0; ks < 8; ks++) {
                uint32_t kf[4][4];
#pragma unroll
                for (int p = 0; p < 4; p++)
                    ldsm_x4(kf[p], bKh + p * (16 * LDS_ * 4) + ks * 32);
#pragma unroll
                for (int p = 0; p < 4; p++) {
                    mma8(s[0][2 * p],     qa[0][ks], &kf[p][0]);
                    mma8(s[0][2 * p + 1], qa[0][ks], &kf[p][2]);
                    mma8(s[1][2 * p],     qa[1][ks], &kf[p][0]);
                    mma8(s[1][2 * p + 1], qa[1][ks], &kf[p][2]);
                }
            }

            // Scale + mask (reference semantics)
            if (!causal) {
                bool mz[8][2];
#pragma unroll
                for (int nt = 0; nt < 8; nt++)
#pragma unroll
                    for (int e = 0; e < 2; e++)
                        mz[nt][e] = (mb[t0 + nt * 8 + 2 * tg + e] == 0.f);
#pragma unroll
                for (int mt = 0; mt < 2; mt++)
#pragma unroll
                    for (int nt = 0; nt < 8; nt++)
#pragma unroll
                        for (int e = 0; e < 2; e++) {
                            s[mt][nt][e]     = mz[nt][e] ? -1e30f : s[mt][nt][e] * 0.125f;
                            s[mt][nt][2 + e] = mz[nt][e] ? -1e30f : s[mt][nt][2 + e] * 0.125f;
                        }
            } else {
#pragma unroll
                for (int mt = 0; mt < 2; mt++) {
                    int rg0 = s0 + warp * 32 + mt * 16 + g;
                    int rg1 = rg0 + 8;
#pragma unroll
                    for (int nt = 0; nt < 8; nt++) {
#pragma unroll
                        for (int e = 0; e < 2; e++) {
                            int t = t0 + nt * 8 + 2 * tg + e;
                            float v0 = s[mt][nt][e] * 0.125f;
                            float v1 = s[mt][nt][2 + e] * 0.125f;
                            if (mb[(size_t)rg0 * TT + t] == 0.f && t <= rg0) v0 = -1e30f;
                            if (mb[(size_t)rg1 * TT + t] == 0.f && t <= rg1) v1 = -1e30f;
                            s[mt][nt][e] = v0;
                            s[mt][nt][2 + e] = v1;
                        }
                    }
                }
            }

            // Online softmax; write P into Qs region (own warp rows only)
#pragma unroll
            for (int mt = 0; mt < 2; mt++) {
                float rm0 = -1e30f, rm1 = -1e30f;
#pragma unroll
                for (int nt = 0; nt < 8; nt++) {
                    rm0 = fmaxf(rm0, fmaxf(s[mt][nt][0], s[mt][nt][1]));
                    rm1 = fmaxf(rm1, fmaxf(s[mt][nt][2], s[mt][nt][3]));
                }
                rm0 = fmaxf(rm0, __shfl_xor_sync(0xffffffffu, rm0, 1));
                rm0 = fmaxf(rm0, __shfl_xor_sync(0xffffffffu, rm0, 2));
                rm1 = fmaxf(rm1, __shfl_xor_sync(0xffffffffu, rm1, 1));
                rm1 = fmaxf(rm1, __shfl_xor_sync(0xffffffffu, rm1, 2));

                float mn0 = fmaxf(mr[mt][0], rm0);
                float mn1 = fmaxf(mr[mt][1], rm1);
                float a0 = __expf(mr[mt][0] - mn0);
                float a1 = __expf(mr[mt][1] - mn1);
                mr[mt][0] = mn0; mr[mt][1] = mn1;

                int rb = warp * 32 + mt * 16;
                float ls0 = 0.f, ls1 = 0.f;
#pragma unroll
                for (int nt = 0; nt < 8; nt++) {
                    float p00 = __expf(s[mt][nt][0] - mn0);
                    float p01 = __expf(s[mt][nt][1] - mn0);
                    float p10 = __expf(s[mt][nt][2] - mn1);
                    float p11 = __expf(s[mt][nt][3] - mn1);
                    ls0 += p00 + p01;
                    ls1 += p10 + p11;
                    int cb = nt * 8 + 2 * tg;
                    *(float2*)&Qs[(rb + g) * LDS_ + cb] =
                        make_float2(f2tf_f(p00), f2tf_f(p01));
                    *(float2*)&Qs[(rb + g + 8) * LDS_ + cb] =
                        make_float2(f2tf_f(p10), f2tf_f(p11));
                    o[mt][nt][0] *= a0; o[mt][nt][1] *= a0;
                    o[mt][nt][2] *= a1; o[mt][nt][3] *= a1;
                }
                ls0 += __shfl_xor_sync(0xffffffffu, ls0, 1);
                ls0 += __shfl_xor_sync(0xffffffffu, ls0, 2);
                ls1 += __shfl_xor_sync(0xffffffffu, ls1, 1);
                ls1 += __shfl_xor_sync(0xffffffffu, ls1, 2);
                lr[mt][0] = lr[mt][0] * a0 + ls0;
                lr[mt][1] = lr[mt][1] * a1 + ls1;
            }
            __syncwarp();   // P visible within warp before LDSM of own rows

            // O += P V
#pragma unroll
            for (int ks = 0; ks < 8; ks++) {
                uint32_t pf[2][4], vf[4][4];
                ldsm_x4(pf[0], aP0 + ks * 32);
                ldsm_x4(pf[1], aP1 + ks * 32);
#pragma unroll
                for (int p = 0; p < 4; p++)
                    ldsm_x4(vf[p], bVh + p * (16 * VST * 4) + ks * 32);
#pragma unroll
                for (int p = 0; p < 4; p++) {
                    mma8(o[0][2 * p],     pf[0], &vf[p][0]);
                    mma8(o[0][2 * p + 1], pf[0], &vf[p][2]);
                    mma8(o[1][2 * p],     pf[1], &vf[p][0]);
                    mma8(o[1][2 * p + 1], pf[1], &vf[p][2]);
                }
            }
            __syncwarp();   // own P rows fully consumed before next half rewrites
        }
    }

    // Normalize and write out (raw fp32; out-GEMM rounds at its own input)
#pragma unroll
    for (int mt = 0; mt < 2; mt++) {
        float i0 = 1.f / lr[mt][0];
        float i1 = 1.f / lr[mt][1];
        const size_t ob = ((size_t)b * SS + s0 + warp * 32 + mt * 16) * CHN + h * HD;
#pragma unroll
        for (int nt = 0; nt < 8; nt++) {
            int col = nt * 8 + 2 * tg;
            float2 v0 = make_float2(o[mt][nt][0] * i0, o[mt][nt][1] * i0);
            float2 v1 = make_float2(o[mt][nt][2] * i1, o[mt][nt][3] * i1);
            *(float2*)&g_A[ob + (size_t)g * CHN + col] = v0;
            *(float2*)&g_A[ob + (size_t)(g + 8) * CHN + col] = v1;
        }
    }
}

// ---------------- launch ----------------
extern "C" void kernel_launch(void* const* d_in, const int* in_sizes, int n_in,
                              void* d_out, int out_size)
{
    const float* query = (const float*)d_in[0];
    const float* key   = (const float*)d_in[1];
    const float* value = (const float*)d_in[2];
    const float* mask  = (const float*)d_in[3];
    const float* Wq    = (const float*)d_in[4];
    const float* bq    = (const float*)d_in[5];
    const float* Wk    = (const float*)d_in[6];
    const float* bk    = (const float*)d_in[7];
    const float* Wv    = (const float*)d_in[8];
    const float* bv    = (const float*)d_in[9];
    const float* Wo    = (const float*)d_in[10];
    const float* bo    = (const float*)d_in[11];
    const int*   causal = (const int*)d_in[12];
    float* out = (float*)d_out;

    float *Qp, *Kp, *Vp, *Ap;
    cudaGetSymbolAddress((void**)&Qp, g_Q);
    cudaGetSymbolAddress((void**)&Kp, g_K);
    cudaGetSymbolAddress((void**)&Vp, g_V);
    cudaGetSymbolAddress((void**)&Ap, g_A);

    const int gsmem = 2 * GSTGB;   // 73,728 B
    cudaFuncSetAttribute(qkv_gemm_kernel,
                         cudaFuncAttributeMaxDynamicSharedMemorySize, gsmem);
    cudaFuncSetAttribute(out_gemm_kernel,
                         cudaFuncAttributeMaxDynamicSharedMemorySize, gsmem);

    qkv_gemm_kernel<<<dim3(8, 32, 3), 256, gsmem>>>(
        query, key, value, Wq, Wk, Wv, bq, bk, bv, Qp, Kp, Vp);

    const int fsmem = FSMEM_F * (int)sizeof(float);   // 103,424 B (2 CTAs/SM fit)
    cudaFuncSetAttribute(flash_attn_kernel,
                         cudaFuncAttributeMaxDynamicSharedMemorySize, fsmem);
    flash_attn_kernel<<<dim3(SS / 128, NH, BB), 128, fsmem>>>(mask, causal);

    out_gemm_kernel<<<dim3(8, 32), 256, gsmem>>>(Ap, Wo, bo, out, mask);
}

// round 13
// speedup vs baseline: 1.0272x; 1.0272x over previous
#include <cuda_runtime.h>
#include <cstdint>

// Problem constants
#define BB   2
#define SS   2048
#define TT   2048
#define CHN  1024
#define NH   16
#define HD   64
#define MM   (BB * SS)   // 4096 rows

// Scratch (device globals: allocation-free rule)
__device__ float g_Q[(size_t)MM * CHN];
__device__ float g_K[(size_t)MM * CHN];
__device__ float g_V[(size_t)MM * CHN];
__device__ float g_A[(size_t)MM * CHN];

// ---------------- helpers ----------------
__device__ __forceinline__ uint32_t f2tf(float x) {
    uint32_t u;
    asm("cvt.rna.tf32.f32 %0, %1;\n" : "=r"(u) : "f"(x));
    return u;
}
__device__ __forceinline__ float f2tf_f(float x) {
    return __uint_as_float(f2tf(x));
}
__device__ __forceinline__ uint32_t fu(float x) { return __float_as_uint(x); }

__device__ __forceinline__ float4 tf4(float4 v) {
    return make_float4(f2tf_f(v.x), f2tf_f(v.y), f2tf_f(v.z), f2tf_f(v.w));
}

__device__ __forceinline__ uint32_t smem_u32(const void* p) {
    return (uint32_t)__cvta_generic_to_shared(p);
}

__device__ __forceinline__ void cpa16(uint32_t dst_smem, const float* src) {
    asm volatile("cp.async.cg.shared.global [%0], [%1], 16;\n"
                 :: "r"(dst_smem), "l"(src));
}
__device__ __forceinline__ void cp_commit() {
    asm volatile("cp.async.commit_group;\n");
}
__device__ __forceinline__ void cp_wait0() {
    asm volatile("cp.async.wait_group 0;\n");
}

// D(16x8) += A(16x8, tf32, row) * B(8x8, tf32, col)
__device__ __forceinline__ void mma8(float c[4], const uint32_t a[4], const uint32_t b[2]) {
    asm volatile(
        "mma.sync.aligned.m16n8k8.row.col.f32.tf32.tf32.f32 "
        "{%0,%1,%2,%3}, {%4,%5,%6,%7}, {%8,%9}, {%0,%1,%2,%3};\n"
        : "+f"(c[0]), "+f"(c[1]), "+f"(c[2]), "+f"(c[3])
        : "r"(a[0]), "r"(a[1]), "r"(a[2]), "r"(a[3]), "r"(b[0]), "r"(b[1]));
}

// ldmatrix x4: 4 8x8-b16 matrices (= 8x4-tf32 blocks); exact tf32 frag layout.
__device__ __forceinline__ void ldsm_x4(uint32_t r[4], uint32_t saddr) {
    asm volatile("ldmatrix.sync.aligned.m8n8.x4.shared.b16 {%0,%1,%2,%3}, [%4];"
        : "=r"(r[0]), "=r"(r[1]), "=r"(r[2]), "=r"(r[3]) : "r"(saddr));
}

// ---------------- GEMM body (R9-proven): C[4096,1024] = X @ W + bias ----------------
// BM=128, BN=128, BK=32, 256 threads (8 warps = 4m x 2n), LDSM fragments,
// double-buffered smem + register prefetch.
// ROUND_OUT: round result to tf32 at store (Q/K/V -> flash fills are byte copies;
// f2tf idempotent, downstream bit-identical). Final out: false.
#define GXF   (128 * 36)
#define GWF   (128 * 36)
#define GSTG  (GXF + GWF)
#define GSTGB (GSTG * 4)

template <bool ROUND_OUT>
__device__ __forceinline__ void gemm_body(
    const float* __restrict__ X, const float* __restrict__ W,
    const float* __restrict__ bias, float* __restrict__ C,
    const float* __restrict__ maskScale, float* gsm)
{
    const uint32_t gsb = smem_u32(gsm);

    const int tid  = threadIdx.x;
    const int lane = tid & 31;
    const int warp = tid >> 5;
    const int g    = lane >> 2;
    const int tg   = lane & 3;
    const int wm   = warp >> 1;   // 0..3
    const int wn   = warp & 1;    // 0..1
    const int m0   = blockIdx.y * 128;
    const int n0   = blockIdx.x * 128;

    const uint32_t a_thr = (uint32_t)(((wm * 32 + (lane & 15)) * 36 + (lane >> 4) * 4) * 4);
    const uint32_t b_thr = (uint32_t)(((wn * 64 + ((lane >> 4) * 8) + (lane & 7)) * 36
                                      + (((lane >> 3) & 1) * 4)) * 4);

    float4 px[4], pw[4];

    auto ldg_tile = [&](int kt) {
#pragma unroll
        for (int i = 0; i < 4; i++) {
            int idx = i * 256 + tid;
            int xr = idx >> 3, xc = (idx & 7) * 4;
            px[i] = *(const float4*)&X[(size_t)(m0 + xr) * 1024 + kt + xc];
        }
        const int bn = tid & 127;
        const int bh = tid >> 7;
#pragma unroll
        for (int j = 0; j < 4; j++) {
            int kq = bh * 4 + j;
            pw[j] = make_float4(
                W[(size_t)(kt + kq * 4 + 0) * 1024 + n0 + bn],
                W[(size_t)(kt + kq * 4 + 1) * 1024 + n0 + bn],
                W[(size_t)(kt + kq * 4 + 2) * 1024 + n0 + bn],
                W[(size_t)(kt + kq * 4 + 3) * 1024 + n0 + bn]);
        }
    };
    auto sts_tile = [&](int st) {
        float* Xs = gsm + st * GSTG;
        float* Ws = Xs + GXF;
#pragma unroll
        for (int i = 0; i < 4; i++) {
            int idx = i * 256 + tid;
            int xr = idx >> 3, xc = (idx & 7) * 4;
            *(float4*)&Xs[xr * 36 + xc] = tf4(px[i]);
        }
        const int bn = tid & 127;
        const int bh = tid >> 7;
#pragma unroll
        for (int j = 0; j < 4; j++) {
            int kq = bh * 4 + j;
            *(float4*)&Ws[bn * 36 + kq * 4] = tf4(pw[j]);
        }
    };

    float c[2][8][4];
#pragma unroll
    for (int mt = 0; mt < 2; mt++)
#pragma unroll
        for (int nt = 0; nt < 8; nt++)
#pragma unroll
            for (int e = 0; e < 4; e++) c[mt][nt][e] = 0.f;

    ldg_tile(0);
    sts_tile(0);
    __syncthreads();

    for (int kt = 0; kt < 32; kt++) {
        if (kt + 1 < 32) ldg_tile((kt + 1) * 32);

        const uint32_t xa = gsb + (kt & 1) * GSTGB + a_thr;
        const uint32_t wa = gsb + (kt & 1) * GSTGB + GXF * 4 + b_thr;

#pragma unroll
        for (int kk = 0; kk < 4; kk++) {
            uint32_t af[2][4], bf[4][4];
            ldsm_x4(af[0], xa + kk * 32);
            ldsm_x4(af[1], xa + 16 * 36 * 4 + kk * 32);
#pragma unroll
            for (int p = 0; p < 4; p++)
                ldsm_x4(bf[p], wa + p * (16 * 36 * 4) + kk * 32);
#pragma unroll
            for (int p = 0; p < 4; p++) {
                mma8(c[0][2 * p],     af[0], &bf[p][0]);
                mma8(c[0][2 * p + 1], af[0], &bf[p][2]);
                mma8(c[1][2 * p],     af[1], &bf[p][0]);
                mma8(c[1][2 * p + 1], af[1], &bf[p][2]);
            }
        }

        if (kt + 1 < 32) sts_tile((kt + 1) & 1);
        __syncthreads();
    }

#pragma unroll
    for (int mt = 0; mt < 2; mt++) {
        int r0 = m0 + wm * 32 + mt * 16 + g;
        int r1 = r0 + 8;
        float sc0 = 1.f, sc1 = 1.f;
        if (maskScale) {
            sc0 = maskScale[(size_t)r0 * TT];
            sc1 = maskScale[(size_t)r1 * TT];
        }
#pragma unroll
        for (int nt = 0; nt < 8; nt++) {
            int col = n0 + wn * 64 + nt * 8 + 2 * tg;
            float b0 = bias[col], b1 = bias[col + 1];
            float v00 = (c[mt][nt][0] + b0) * sc0;
            float v01 = (c[mt][nt][1] + b1) * sc0;
            float v10 = (c[mt][nt][2] + b0) * sc1;
            float v11 = (c[mt][nt][3] + b1) * sc1;
            if (ROUND_OUT) {
                v00 = f2tf_f(v00); v01 = f2tf_f(v01);
                v10 = f2tf_f(v10); v11 = f2tf_f(v11);
            }
            *(float2*)&C[(size_t)r0 * 1024 + col] = make_float2(v00, v01);
            *(float2*)&C[(size_t)r1 * 1024 + col] = make_float2(v10, v11);
        }
    }
}

// Fused QKV projections: blockIdx.z picks (input, weight, bias, output)
__global__ void __launch_bounds__(256, 2) qkv_gemm_kernel(
    const float* __restrict__ query, const float* __restrict__ key,
    const float* __restrict__ value,
    const float* __restrict__ Wq, const float* __restrict__ Wk,
    const float* __restrict__ Wv,
    const float* __restrict__ bq, const float* __restrict__ bk,
    const float* __restrict__ bv,
    float* __restrict__ Qp, float* __restrict__ Kp, float* __restrict__ Vp)
{
    extern __shared__ float gsm[];
    const int z = blockIdx.z;   // uniform per CTA
    const float* X    = (z == 0) ? query : (z == 1) ? key : value;
    const float* W    = (z == 0) ? Wq    : (z == 1) ? Wk  : Wv;
    const float* bias = (z == 0) ? bq    : (z == 1) ? bk  : bv;
    float*       C    = (z == 0) ? Qp    : (z == 1) ? Kp  : Vp;
    gemm_body<true>(X, W, bias, C, nullptr, gsm);   // tf32-rounded outputs
}

// Output projection (with mask scaling); final answer stays full fp32.
__global__ void __launch_bounds__(256, 2) out_gemm_kernel(
    const float* __restrict__ X, const float* __restrict__ W,
    const float* __restrict__ bias, float* __restrict__ C,
    const float* __restrict__ maskScale)
{
    extern __shared__ float gsm[];
    gemm_body<false>(X, W, bias, C, maskScale, gsm);
}

// ---------------- Flash attention v7: R9 structure + cp.async K double buffer ----
// Grid: (S/128, H, B). 128 threads = 4 warps; warp owns 2 m-tiles of 16 rows.
// Q/K/V pre-rounded tf32 -> fills are byte copies. K tile double-buffered via
// cp.async issued right after the fill barrier, overlapping the whole compute
// phase. V transposed fill stays synchronous. P round-trips through Qs.
#define LDS_  68
#define FCH   64
#define NCH   (TT / FCH)
#define KSTG  (64 * LDS_)   // floats per K stage
// smem: Qs 128x68 | Ks[2] 64x68 | Vs 64x68  = 21,760 floats = 87,040 B

__global__ void __launch_bounds__(128) flash_attn_kernel(
    const float* __restrict__ mask, const int* __restrict__ causal_p)
{
    extern __shared__ float sm[];
    float* Qs = sm;                       // 128 x 68 (P reuses own rows)
    float* Ks = sm + 128 * LDS_;          // 2 stages x 64 x 68  [t][d]
    float* Vs = sm + 128 * LDS_ + 2 * KSTG;   // 64 x 68  [d][t]

    const int tid  = threadIdx.x;
    const int lane = tid & 31;
    const int warp = tid >> 5;
    const int g    = lane >> 2;
    const int tg   = lane & 3;
    const int s0   = blockIdx.x * 128;
    const int h    = blockIdx.y;
    const int b    = blockIdx.z;
    const int causal = causal_p[0];

    const uint32_t Qs_u = smem_u32(Qs);
    const uint32_t Ks_u = smem_u32(Ks);
    const uint32_t Vs_u = smem_u32(Vs);

    const uint32_t bKthr = (uint32_t)(((((lane >> 4) * 8) + (lane & 7)) * LDS_
                                       + (((lane >> 3) & 1) * 4)) * 4);
    const uint32_t bV = Vs_u + (uint32_t)(((((lane >> 4) * 8) + (lane & 7)) * LDS_
                                           + (((lane >> 3) & 1) * 4)) * 4);
    const uint32_t aP0 = Qs_u + (uint32_t)(((warp * 32 + (lane & 15)) * LDS_
                                            + ((lane >> 4) * 4)) * 4);
    const uint32_t aP1 = aP0 + (uint32_t)(16 * LDS_ * 4);

    // K-stage fill via cp.async: 8 x 16B per thread (64 rows x 64 d)
    auto issue_k = [&](int ic, int st) {
        const size_t off = ((size_t)b * TT + ic * FCH) * CHN + h * HD;
        const uint32_t kb = Ks_u + (uint32_t)(st * KSTG * 4);
#pragma unroll
        for (int i = 0; i < 8; i++) {
            int idx = i * 128 + tid;
            int r = idx >> 4, cc = (idx & 15) * 4;
            cpa16(kb + (uint32_t)((r * LDS_ + cc) * 4),
                  &g_K[off + (size_t)r * CHN + cc]);
        }
        cp_commit();
    };

    // Load Q tile [128 x 64] (pre-rounded; plain copy) + kick off K chunk 0
    const size_t qoff = ((size_t)b * SS + s0) * CHN + h * HD;
#pragma unroll
    for (int i = 0; i < 16; i++) {
        int idx = i * 128 + tid;
        int r = idx >> 4, cc = (idx & 15) * 4;
        *(float4*)&Qs[r * LDS_ + cc] = *(const float4*)&g_Q[qoff + (size_t)r * CHN + cc];
    }
    issue_k(0, 0);
    __syncthreads();

    uint32_t qa[2][8][4];
#pragma unroll
    for (int mt = 0; mt < 2; mt++) {
        uint32_t base = (mt == 0) ? aP0 : aP1;
#pragma unroll
        for (int j = 0; j < 8; j++) ldsm_x4(qa[mt][j], base + j * 32);
    }

    float o[2][8][4];
#pragma unroll
    for (int mt = 0; mt < 2; mt++)
#pragma unroll
        for (int nt = 0; nt < 8; nt++)
#pragma unroll
            for (int e = 0; e < 4; e++) o[mt][nt][e] = 0.f;
    float mr[2][2] = {{-1e30f, -1e30f}, {-1e30f, -1e30f}};
    float lr[2][2] = {{0.f, 0.f}, {0.f, 0.f}};

    const float* mb = mask + (size_t)b * SS * TT;
    const int vd  = tid & 63;
    const int vth = tid >> 6;

    for (int ic = 0; ic < NCH; ic++) {
        const int t0 = ic * FCH;
        const int st = ic & 1;
        __syncthreads();   // all warps done reading previous K/V buffers

        // V fill transposed [d][t] (pre-rounded; plain copy)
        const size_t kvoff = ((size_t)b * TT + t0) * CHN + h * HD;
#pragma unroll
        for (int q8 = 0; q8 < 8; q8++) {
            int q = vth * 8 + q8;
            float4 vv = make_float4(
                g_V[kvoff + (size_t)(q * 4 + 0) * CHN + vd],
                g_V[kvoff + (size_t)(q * 4 + 1) * CHN + vd],
                g_V[kvoff + (size_t)(q * 4 + 2) * CHN + vd],
                g_V[kvoff + (size_t)(q * 4 + 3) * CHN + vd]);
            *(float4*)&Vs[vd * LDS_ + q * 4] = vv;
        }
        cp_wait0();        // this thread's K(ic) copies complete
        __syncthreads();   // K(ic) + V(ic) visible to all warps

        // Kick off K(ic+1) into the other stage; overlaps compute below.
        // Safe: Ks[st^1]'s last readers (chunk ic-1) finished before the
        // top-of-loop barrier of THIS iteration.
        if (ic + 1 < NCH) issue_k(ic + 1, st ^ 1);

        const uint32_t bK = Ks_u + (uint32_t)(st * KSTG * 4) + bKthr;

        // S = Q K^T
        float s[2][8][4];
#pragma unroll
        for (int mt = 0; mt < 2; mt++)
#pragma unroll
            for (int nt = 0; nt < 8; nt++)
#pragma unroll
                for (int e = 0; e < 4; e++) s[mt][nt][e] = 0.f;
#pragma unroll
        for (int ks = 0; ks < 8; ks++) {
            uint32_t kf[4][4];
#pragma unroll
            for (int p = 0; p < 4; p++)
                ldsm_x4(kf[p], bK + p * (16 * LDS_ * 4) + ks * 32);
#pragma unroll
            for (int p = 0; p < 4; p++) {
                mma8(s[0][2 * p],     qa[0][ks], &kf[p][0]);
                mma8(s[0][2 * p + 1], qa[0][ks], &kf[p][2]);
                mma8(s[1][2 * p],     qa[1][ks], &kf[p][0]);
                mma8(s[1][2 * p + 1], qa[1][ks], &kf[p][2]);
            }
        }

        // Scale + mask (reference semantics)
        if (!causal) {
            bool mz[8][2];
#pragma unroll
            for (int nt = 0; nt < 8; nt++)
#pragma unroll
                for (int e = 0; e < 2; e++)
                    mz[nt][e] = (mb[t0 + nt * 8 + 2 * tg + e] == 0.f);
#pragma unroll
            for (int mt = 0; mt < 2; mt++)
#pragma unroll
                for (int nt = 0; nt < 8; nt++)
#pragma unroll
                    for (int e = 0; e < 2; e++) {
                        s[mt][nt][e]     = mz[nt][e] ? -1e30f : s[mt][nt][e] * 0.125f;
                        s[mt][nt][2 + e] = mz[nt][e] ? -1e30f : s[mt][nt][2 + e] * 0.125f;
                    }
        } else {
#pragma unroll
            for (int mt = 0; mt < 2; mt++) {
                int rg0 = s0 + warp * 32 + mt * 16 + g;
                int rg1 = rg0 + 8;
#pragma unroll
                for (int nt = 0; nt < 8; nt++) {
#pragma unroll
                    for (int e = 0; e < 2; e++) {
                        int t = t0 + nt * 8 + 2 * tg + e;
                        float v0 = s[mt][nt][e] * 0.125f;
                        float v1 = s[mt][nt][2 + e] * 0.125f;
                        if (mb[(size_t)rg0 * TT + t] == 0.f && t <= rg0) v0 = -1e30f;
                        if (mb[(size_t)rg1 * TT + t] == 0.f && t <= rg1) v1 = -1e30f;
                        s[mt][nt][e] = v0;
                        s[mt][nt][2 + e] = v1;
                    }
                }
            }
        }

        // Online softmax; write P into Qs region (own warp rows only)
#pragma unroll
        for (int mt = 0; mt < 2; mt++) {
            float rm0 = -1e30f, rm1 = -1e30f;
#pragma unroll
            for (int nt = 0; nt < 8; nt++) {
                rm0 = fmaxf(rm0, fmaxf(s[mt][nt][0], s[mt][nt][1]));
                rm1 = fmaxf(rm1, fmaxf(s[mt][nt][2], s[mt][nt][3]));
            }
            rm0 = fmaxf(rm0, __shfl_xor_sync(0xffffffffu, rm0, 1));
            rm0 = fmaxf(rm0, __shfl_xor_sync(0xffffffffu, rm0, 2));
            rm1 = fmaxf(rm1, __shfl_xor_sync(0xffffffffu, rm1, 1));
            rm1 = fmaxf(rm1, __shfl_xor_sync(0xffffffffu, rm1, 2));

            float mn0 = fmaxf(mr[mt][0], rm0);
            float mn1 = fmaxf(mr[mt][1], rm1);
            float a0 = __expf(mr[mt][0] - mn0);
            float a1 = __expf(mr[mt][1] - mn1);
            mr[mt][0] = mn0; mr[mt][1] = mn1;

            int rb = warp * 32 + mt * 16;
            float ls0 = 0.f, ls1 = 0.f;
#pragma unroll
            for (int nt = 0; nt < 8; nt++) {
                float p00 = __expf(s[mt][nt][0] - mn0);
                float p01 = __expf(s[mt][nt][1] - mn0);
                float p10 = __expf(s[mt][nt][2] - mn1);
                float p11 = __expf(s[mt][nt][3] - mn1);
                ls0 += p00 + p01;
                ls1 += p10 + p11;
                int cb = nt * 8 + 2 * tg;
                *(float2*)&Qs[(rb + g) * LDS_ + cb] =
                    make_float2(f2tf_f(p00), f2tf_f(p01));
                *(float2*)&Qs[(rb + g + 8) * LDS_ + cb] =
                    make_float2(f2tf_f(p10), f2tf_f(p11));
                o[mt][nt][0] *= a0; o[mt][nt][1] *= a0;
                o[mt][nt][2] *= a1; o[mt][nt][3] *= a1;
            }
            ls0 += __shfl_xor_sync(0xffffffffu, ls0, 1);
            ls0 += __shfl_xor_sync(0xffffffffu, ls0, 2);
            ls1 += __shfl_xor_sync(0xffffffffu, ls1, 1);
            ls1 += __shfl_xor_sync(0xffffffffu, ls1, 2);
            lr[mt][0] = lr[mt][0] * a0 + ls0;
            lr[mt][1] = lr[mt][1] * a1 + ls1;
        }
        __syncwarp();   // P visible within warp before LDSM of own rows

        // O += P V
#pragma unroll
        for (int ks = 0; ks < 8; ks++) {
            uint32_t pf[2][4], vf[4][4];
            ldsm_x4(pf[0], aP0 + ks * 32);
            ldsm_x4(pf[1], aP1 + ks * 32);
#pragma unroll
            for (int p = 0; p < 4; p++)
                ldsm_x4(vf[p], bV + p * (16 * LDS_ * 4) + ks * 32);
#pragma unroll
            for (int p = 0; p < 4; p++) {
                mma8(o[0][2 * p],     pf[0], &vf[p][0]);
                mma8(o[0][2 * p + 1], pf[0], &vf[p][2]);
                mma8(o[1][2 * p],     pf[1], &vf[p][0]);
                mma8(o[1][2 * p + 1], pf[1], &vf[p][2]);
            }
        }
    }

    // Normalize and write out (raw fp32; out-GEMM rounds its own inputs)
#pragma unroll
    for (int mt = 0; mt < 2; mt++) {
        float i0 = 1.f / lr[mt][0];
        float i1 = 1.f / lr[mt][1];
        const size_t ob = ((size_t)b * SS + s0 + warp * 32 + mt * 16) * CHN + h * HD;
#pragma unroll
        for (int nt = 0; nt < 8; nt++) {
            int col = nt * 8 + 2 * tg;
            float2 v0 = make_float2(o[mt][nt][0] * i0, o[mt][nt][1] * i0);
            float2 v1 = make_float2(o[mt][nt][2] * i1, o[mt][nt][3] * i1);
            *(float2*)&g_A[ob + (size_t)g * CHN + col] = v0;
            *(float2*)&g_A[ob + (size_t)(g + 8) * CHN + col] = v1;
        }
    }
}

// ---------------- launch ----------------
extern "C" void kernel_launch(void* const* d_in, const int* in_sizes, int n_in,
                              void* d_out, int out_size)
{
    const float* query = (const float*)d_in[0];
    const float* key   = (const float*)d_in[1];
    const float* value = (const float*)d_in[2];
    const float* mask  = (const float*)d_in[3];
    const float* Wq    = (const float*)d_in[4];
    const float* bq    = (const float*)d_in[5];
    const float* Wk    = (const float*)d_in[6];
    const float* bk    = (const float*)d_in[7];
    const float* Wv    = (const float*)d_in[8];
    const float* bv    = (const float*)d_in[9];
    const float* Wo    = (const float*)d_in[10];
    const float* bo    = (const float*)d_in[11];
    const int*   causal = (const int*)d_in[12];
    float* out = (float*)d_out;

    float *Qp, *Kp, *Vp, *Ap;
    cudaGetSymbolAddress((void**)&Qp, g_Q);
    cudaGetSymbolAddress((void**)&Kp, g_K);
    cudaGetSymbolAddress((void**)&Vp, g_V);
    cudaGetSymbolAddress((void**)&Ap, g_A);

    const int gsmem = 2 * GSTGB;   // 73,728 B
    cudaFuncSetAttribute(qkv_gemm_kernel,
                         cudaFuncAttributeMaxDynamicSharedMemorySize, gsmem);
    cudaFuncSetAttribute(out_gemm_kernel,
                         cudaFuncAttributeMaxDynamicSharedMemorySize, gsmem);

    qkv_gemm_kernel<<<dim3(8, 32, 3), 256, gsmem>>>(
        query, key, value, Wq, Wk, Wv, bq, bk, bv, Qp, Kp, Vp);

    const int fsmem = (128 * LDS_ + 2 * KSTG + 64 * LDS_) * (int)sizeof(float); // 87,040 B
    cudaFuncSetAttribute(flash_attn_kernel,
                         cudaFuncAttributeMaxDynamicSharedMemorySize, fsmem);
    flash_attn_kernel<<<dim3(SS / 128, NH, BB), 128, fsmem>>>(mask, causal);

    out_gemm_kernel<<<dim3(8, 32), 256, gsmem>>>(Ap, Wo, bo, out, mask);
}

// round 14
// speedup vs baseline: 1.0458x; 1.0181x over previous
#include <cuda_runtime.h>
#include <cstdint>

// Problem constants
#define BB   2
#define SS   2048
#define TT   2048
#define CHN  1024
#define NH   16
#define HD   64
#define MM   (BB * SS)   // 4096 rows

// Scratch (device globals: allocation-free rule)
// g_V holds V TRANSPOSED: Vt[((b*NH+h)*HD + d) * TT + t]
__device__ float g_Q[(size_t)MM * CHN];
__device__ float g_K[(size_t)MM * CHN];
__device__ float g_V[(size_t)MM * CHN];
__device__ float g_A[(size_t)MM * CHN];

// ---------------- helpers ----------------
__device__ __forceinline__ uint32_t f2tf(float x) {
    uint32_t u;
    asm("cvt.rna.tf32.f32 %0, %1;\n" : "=r"(u) : "f"(x));
    return u;
}
__device__ __forceinline__ float f2tf_f(float x) {
    return __uint_as_float(f2tf(x));
}
__device__ __forceinline__ uint32_t fu(float x) { return __float_as_uint(x); }

__device__ __forceinline__ float4 tf4(float4 v) {
    return make_float4(f2tf_f(v.x), f2tf_f(v.y), f2tf_f(v.z), f2tf_f(v.w));
}

__device__ __forceinline__ uint32_t smem_u32(const void* p) {
    return (uint32_t)__cvta_generic_to_shared(p);
}

__device__ __forceinline__ void cpa16(uint32_t dst_smem, const float* src) {
    asm volatile("cp.async.cg.shared.global [%0], [%1], 16;\n"
                 :: "r"(dst_smem), "l"(src));
}
__device__ __forceinline__ void cp_commit() {
    asm volatile("cp.async.commit_group;\n");
}
__device__ __forceinline__ void cp_wait0() {
    asm volatile("cp.async.wait_group 0;\n");
}

// D(16x8) += A(16x8, tf32, row) * B(8x8, tf32, col)
__device__ __forceinline__ void mma8(float c[4], const uint32_t a[4], const uint32_t b[2]) {
    asm volatile(
        "mma.sync.aligned.m16n8k8.row.col.f32.tf32.tf32.f32 "
        "{%0,%1,%2,%3}, {%4,%5,%6,%7}, {%8,%9}, {%0,%1,%2,%3};\n"
        : "+f"(c[0]), "+f"(c[1]), "+f"(c[2]), "+f"(c[3])
        : "r"(a[0]), "r"(a[1]), "r"(a[2]), "r"(a[3]), "r"(b[0]), "r"(b[1]));
}

// ldmatrix x4: 4 8x8-b16 matrices (= 8x4-tf32 blocks); exact tf32 frag layout.
__device__ __forceinline__ void ldsm_x4(uint32_t r[4], uint32_t saddr) {
    asm volatile("ldmatrix.sync.aligned.m8n8.x4.shared.b16 {%0,%1,%2,%3}, [%4];"
        : "=r"(r[0]), "=r"(r[1]), "=r"(r[2]), "=r"(r[3]) : "r"(saddr));
}

// ---------------- GEMM body (R9-proven): C[4096,1024] = X @ W + bias ----------------
// BM=128, BN=128, BK=32, 256 threads, LDSM fragments, double-buffered smem.
// OUT_MODE: 0 = plain fp32 + optional maskScale (final projection)
//           1 = tf32-rounded (Q, K: flash fills become byte copies)
//           2 = tf32-rounded + TRANSPOSED V layout Vt[(b*16+h)*64+d][t]
#define GXF   (128 * 36)
#define GWF   (128 * 36)
#define GSTG  (GXF + GWF)
#define GSTGB (GSTG * 4)

template <int OUT_MODE>
__device__ __forceinline__ void gemm_body(
    const float* __restrict__ X, const float* __restrict__ W,
    const float* __restrict__ bias, float* __restrict__ C,
    const float* __restrict__ maskScale, float* gsm)
{
    const uint32_t gsb = smem_u32(gsm);

    const int tid  = threadIdx.x;
    const int lane = tid & 31;
    const int warp = tid >> 5;
    const int g    = lane >> 2;
    const int tg   = lane & 3;
    const int wm   = warp >> 1;   // 0..3
    const int wn   = warp & 1;    // 0..1
    const int m0   = blockIdx.y * 128;
    const int n0   = blockIdx.x * 128;

    const uint32_t a_thr = (uint32_t)(((wm * 32 + (lane & 15)) * 36 + (lane >> 4) * 4) * 4);
    const uint32_t b_thr = (uint32_t)(((wn * 64 + ((lane >> 4) * 8) + (lane & 7)) * 36
                                      + (((lane >> 3) & 1) * 4)) * 4);

    float4 px[4], pw[4];

    auto ldg_tile = [&](int kt) {
#pragma unroll
        for (int i = 0; i < 4; i++) {
            int idx = i * 256 + tid;
            int xr = idx >> 3, xc = (idx & 7) * 4;
            px[i] = *(const float4*)&X[(size_t)(m0 + xr) * 1024 + kt + xc];
        }
        const int bn = tid & 127;
        const int bh = tid >> 7;
#pragma unroll
        for (int j = 0; j < 4; j++) {
            int kq = bh * 4 + j;
            pw[j] = make_float4(
                W[(size_t)(kt + kq * 4 + 0) * 1024 + n0 + bn],
                W[(size_t)(kt + kq * 4 + 1) * 1024 + n0 + bn],
                W[(size_t)(kt + kq * 4 + 2) * 1024 + n0 + bn],
                W[(size_t)(kt + kq * 4 + 3) * 1024 + n0 + bn]);
        }
    };
    auto sts_tile = [&](int st) {
        float* Xs = gsm + st * GSTG;
        float* Ws = Xs + GXF;
#pragma unroll
        for (int i = 0; i < 4; i++) {
            int idx = i * 256 + tid;
            int xr = idx >> 3, xc = (idx & 7) * 4;
            *(float4*)&Xs[xr * 36 + xc] = tf4(px[i]);
        }
        const int bn = tid & 127;
        const int bh = tid >> 7;
#pragma unroll
        for (int j = 0; j < 4; j++) {
            int kq = bh * 4 + j;
            *(float4*)&Ws[bn * 36 + kq * 4] = tf4(pw[j]);
        }
    };

    float c[2][8][4];
#pragma unroll
    for (int mt = 0; mt < 2; mt++)
#pragma unroll
        for (int nt = 0; nt < 8; nt++)
#pragma unroll
            for (int e = 0; e < 4; e++) c[mt][nt][e] = 0.f;

    ldg_tile(0);
    sts_tile(0);
    __syncthreads();

    for (int kt = 0; kt < 32; kt++) {
        if (kt + 1 < 32) ldg_tile((kt + 1) * 32);

        const uint32_t xa = gsb + (kt & 1) * GSTGB + a_thr;
        const uint32_t wa = gsb + (kt & 1) * GSTGB + GXF * 4 + b_thr;

#pragma unroll
        for (int kk = 0; kk < 4; kk++) {
            uint32_t af[2][4], bf[4][4];
            ldsm_x4(af[0], xa + kk * 32);
            ldsm_x4(af[1], xa + 16 * 36 * 4 + kk * 32);
#pragma unroll
            for (int p = 0; p < 4; p++)
                ldsm_x4(bf[p], wa + p * (16 * 36 * 4) + kk * 32);
#pragma unroll
            for (int p = 0; p < 4; p++) {
                mma8(c[0][2 * p],     af[0], &bf[p][0]);
                mma8(c[0][2 * p + 1], af[0], &bf[p][2]);
                mma8(c[1][2 * p],     af[1], &bf[p][0]);
                mma8(c[1][2 * p + 1], af[1], &bf[p][2]);
            }
        }

        if (kt + 1 < 32) sts_tile((kt + 1) & 1);
        __syncthreads();
    }

#pragma unroll
    for (int mt = 0; mt < 2; mt++) {
        int r0 = m0 + wm * 32 + mt * 16 + g;
        int r1 = r0 + 8;
        if (OUT_MODE == 2) {
            // Transposed V store: Vt[(b*16+h)*64+d][t]; whole CTA is one b.
            const size_t bbase = (size_t)(r0 >> 11) * NH * HD;   // b * 1024
            const int t0v = r0 & 2047, t1v = r1 & 2047;
#pragma unroll
            for (int nt = 0; nt < 8; nt++) {
                int col = n0 + wn * 64 + nt * 8 + 2 * tg;
                float b0 = bias[col], b1 = bias[col + 1];
                // row in Vt = b*1024 + h*64 + d = b*1024 + col (h=col>>6, d=col&63)
                const size_t vr0 = (bbase + col) * TT;
                const size_t vr1 = vr0 + TT;
                C[vr0 + t0v] = f2tf_f(c[mt][nt][0] + b0);
                C[vr1 + t0v] = f2tf_f(c[mt][nt][1] + b1);
                C[vr0 + t1v] = f2tf_f(c[mt][nt][2] + b0);
                C[vr1 + t1v] = f2tf_f(c[mt][nt][3] + b1);
            }
        } else {
            float sc0 = 1.f, sc1 = 1.f;
            if (OUT_MODE == 0 && maskScale) {
                sc0 = maskScale[(size_t)r0 * TT];
                sc1 = maskScale[(size_t)r1 * TT];
            }
#pragma unroll
            for (int nt = 0; nt < 8; nt++) {
                int col = n0 + wn * 64 + nt * 8 + 2 * tg;
                float b0 = bias[col], b1 = bias[col + 1];
                float v00 = (c[mt][nt][0] + b0) * sc0;
                float v01 = (c[mt][nt][1] + b1) * sc0;
                float v10 = (c[mt][nt][2] + b0) * sc1;
                float v11 = (c[mt][nt][3] + b1) * sc1;
                if (OUT_MODE == 1) {
                    v00 = f2tf_f(v00); v01 = f2tf_f(v01);
                    v10 = f2tf_f(v10); v11 = f2tf_f(v11);
                }
                *(float2*)&C[(size_t)r0 * 1024 + col] = make_float2(v00, v01);
                *(float2*)&C[(size_t)r1 * 1024 + col] = make_float2(v10, v11);
            }
        }
    }
}

// Fused QKV projections: blockIdx.z picks (input, weight, bias, output)
__global__ void __launch_bounds__(256, 2) qkv_gemm_kernel(
    const float* __restrict__ query, const float* __restrict__ key,
    const float* __restrict__ value,
    const float* __restrict__ Wq, const float* __restrict__ Wk,
    const float* __restrict__ Wv,
    const float* __restrict__ bq, const float* __restrict__ bk,
    const float* __restrict__ bv,
    float* __restrict__ Qp, float* __restrict__ Kp, float* __restrict__ Vp)
{
    extern __shared__ float gsm[];
    const int z = blockIdx.z;   // uniform per CTA
    if (z == 0)      gemm_body<1>(query, Wq, bq, Qp, nullptr, gsm);
    else if (z == 1) gemm_body<1>(key,   Wk, bk, Kp, nullptr, gsm);
    else             gemm_body<2>(value, Wv, bv, Vp, nullptr, gsm);  // transposed Vt
}

// Output projection (with mask scaling); final answer stays full fp32.
__global__ void __launch_bounds__(256, 2) out_gemm_kernel(
    const float* __restrict__ X, const float* __restrict__ W,
    const float* __restrict__ bias, float* __restrict__ C,
    const float* __restrict__ maskScale)
{
    extern __shared__ float gsm[];
    gemm_body<0>(X, W, bias, C, maskScale, gsm);
}

// ---------------- Flash attention v8: fully async double-buffered K AND V ----
// Grid: (S/128, H, B). 128 threads = 4 warps; warp owns 2 m-tiles of 16 rows.
// g_V is pre-transposed Vt -> V fill is a coalesced row copy via cp.async.
// Per chunk: ONE barrier, zero synchronous fill LDGs. P round-trips through Qs.
#define LDS_  68
#define FCH   64
#define NCH   (TT / FCH)
#define KSTG  (64 * LDS_)   // floats per K or V stage
// smem: Qs 128x68 | Ks[2] 64x68 | Vs[2] 64x68 = 26,112 floats = 104,448 B

__global__ void __launch_bounds__(128) flash_attn_kernel(
    const float* __restrict__ mask, const int* __restrict__ causal_p)
{
    extern __shared__ float sm[];
    float* Qs = sm;                            // 128 x 68 (P reuses own rows)
    float* Ks = sm + 128 * LDS_;               // 2 stages x 64 x 68  [t][d]
    float* Vs = sm + 128 * LDS_ + 2 * KSTG;    // 2 stages x 64 x 68  [d][t]

    const int tid  = threadIdx.x;
    const int lane = tid & 31;
    const int warp = tid >> 5;
    const int g    = lane >> 2;
    const int tg   = lane & 3;
    const int s0   = blockIdx.x * 128;
    const int h    = blockIdx.y;
    const int b    = blockIdx.z;
    const int causal = causal_p[0];

    const uint32_t Qs_u = smem_u32(Qs);
    const uint32_t Ks_u = smem_u32(Ks);
    const uint32_t Vs_u = smem_u32(Vs);

    const uint32_t bKthr = (uint32_t)(((((lane >> 4) * 8) + (lane & 7)) * LDS_
                                       + (((lane >> 3) & 1) * 4)) * 4);
    const uint32_t bVthr = bKthr;   // same pattern, Vs stride also LDS_
    const uint32_t aP0 = Qs_u + (uint32_t)(((warp * 32 + (lane & 15)) * LDS_
                                            + ((lane >> 4) * 4)) * 4);
    const uint32_t aP1 = aP0 + (uint32_t)(16 * LDS_ * 4);

    // Fill K[t][d] and V[d][t] stages via cp.async (pre-rounded byte copies).
    auto issue_kv = [&](int ic, int st) {
        const size_t koff = ((size_t)b * TT + ic * FCH) * CHN + h * HD;
        const uint32_t kb = Ks_u + (uint32_t)(st * KSTG * 4);
#pragma unroll
        for (int i = 0; i < 8; i++) {
            int idx = i * 128 + tid;
            int r = idx >> 4, cc = (idx & 15) * 4;
            cpa16(kb + (uint32_t)((r * LDS_ + cc) * 4),
                  &g_K[koff + (size_t)r * CHN + cc]);
        }
        const size_t voff = (((size_t)b * NH + h) * HD) * TT + ic * FCH;
        const uint32_t vb = Vs_u + (uint32_t)(st * KSTG * 4);
#pragma unroll
        for (int i = 0; i < 8; i++) {
            int idx = i * 128 + tid;
            int d = idx >> 4, q = (idx & 15) * 4;
            cpa16(vb + (uint32_t)((d * LDS_ + q) * 4),
                  &g_V[voff + (size_t)d * TT + q]);
        }
        cp_commit();
    };

    // Load Q tile [128 x 64] (pre-rounded; plain copy) + kick off chunk 0
    const size_t qoff = ((size_t)b * SS + s0) * CHN + h * HD;
#pragma unroll
    for (int i = 0; i < 16; i++) {
        int idx = i * 128 + tid;
        int r = idx >> 4, cc = (idx & 15) * 4;
        *(float4*)&Qs[r * LDS_ + cc] = *(const float4*)&g_Q[qoff + (size_t)r * CHN + cc];
    }
    issue_kv(0, 0);
    __syncthreads();

    uint32_t qa[2][8][4];
#pragma unroll
    for (int mt = 0; mt < 2; mt++) {
        uint32_t base = (mt == 0) ? aP0 : aP1;
#pragma unroll
        for (int j = 0; j < 8; j++) ldsm_x4(qa[mt][j], base + j * 32);
    }

    float o[2][8][4];
#pragma unroll
    for (int mt = 0; mt < 2; mt++)
#pragma unroll
        for (int nt = 0; nt < 8; nt++)
#pragma unroll
            for (int e = 0; e < 4; e++) o[mt][nt][e] = 0.f;
    float mr[2][2] = {{-1e30f, -1e30f}, {-1e30f, -1e30f}};
    float lr[2][2] = {{0.f, 0.f}, {0.f, 0.f}};

    const float* mb = mask + (size_t)b * SS * TT;

    for (int ic = 0; ic < NCH; ic++) {
        const int t0 = ic * FCH;
        const int st = ic & 1;

        cp_wait0();        // K/V(ic) copies complete (only group in flight)
        __syncthreads();   // publish K/V(ic); all warps done chunk ic-1 (stage st^1 free)
        if (ic + 1 < NCH) issue_kv(ic + 1, st ^ 1);   // overlaps compute below

        const uint32_t bK = Ks_u + (uint32_t)(st * KSTG * 4) + bKthr;
        const uint32_t bV = Vs_u + (uint32_t)(st * KSTG * 4) + bVthr;

        // S = Q K^T
        float s[2][8][4];
#pragma unroll
        for (int mt = 0; mt < 2; mt++)
#pragma unroll
            for (int nt = 0; nt < 8; nt++)
#pragma unroll
                for (int e = 0; e < 4; e++) s[mt][nt][e] = 0.f;
#pragma unroll
        for (int ks = 0; ks < 8; ks++) {
            uint32_t kf[4][4];
#pragma unroll
            for (int p = 0; p < 4; p++)
                ldsm_x4(kf[p], bK + p * (16 * LDS_ * 4) + ks * 32);
#pragma unroll
            for (int p = 0; p < 4; p++) {
                mma8(s[0][2 * p],     qa[0][ks], &kf[p][0]);
                mma8(s[0][2 * p + 1], qa[0][ks], &kf[p][2]);
                mma8(s[1][2 * p],     qa[1][ks], &kf[p][0]);
                mma8(s[1][2 * p + 1], qa[1][ks], &kf[p][2]);
            }
        }

        // Scale + mask (reference semantics)
        if (!causal) {
            bool mz[8][2];
#pragma unroll
            for (int nt = 0; nt < 8; nt++)
#pragma unroll
                for (int e = 0; e < 2; e++)
                    mz[nt][e] = (mb[t0 + nt * 8 + 2 * tg + e] == 0.f);
#pragma unroll
            for (int mt = 0; mt < 2; mt++)
#pragma unroll
                for (int nt = 0; nt < 8; nt++)
#pragma unroll
                    for (int e = 0; e < 2; e++) {
                        s[mt][nt][e]     = mz[nt][e] ? -1e30f : s[mt][nt][e] * 0.125f;
                        s[mt][nt][2 + e] = mz[nt][e] ? -1e30f : s[mt][nt][2 + e] * 0.125f;
                    }
        } else {
#pragma unroll
            for (int mt = 0; mt < 2; mt++) {
                int rg0 = s0 + warp * 32 + mt * 16 + g;
                int rg1 = rg0 + 8;
#pragma unroll
                for (int nt = 0; nt < 8; nt++) {
#pragma unroll
                    for (int e = 0; e < 2; e++) {
                        int t = t0 + nt * 8 + 2 * tg + e;
                        float v0 = s[mt][nt][e] * 0.125f;
                        float v1 = s[mt][nt][2 + e] * 0.125f;
                        if (mb[(size_t)rg0 * TT + t] == 0.f && t <= rg0) v0 = -1e30f;
                        if (mb[(size_t)rg1 * TT + t] == 0.f && t <= rg1) v1 = -1e30f;
                        s[mt][nt][e] = v0;
                        s[mt][nt][2 + e] = v1;
                    }
                }
            }
        }

        // Online softmax; write P into Qs region (own warp rows only)
#pragma unroll
        for (int mt = 0; mt < 2; mt++) {
            float rm0 = -1e30f, rm1 = -1e30f;
#pragma unroll
            for (int nt = 0; nt < 8; nt++) {
                rm0 = fmaxf(rm0, fmaxf(s[mt][nt][0], s[mt][nt][1]));
                rm1 = fmaxf(rm1, fmaxf(s[mt][nt][2], s[mt][nt][3]));
            }
            rm0 = fmaxf(rm0, __shfl_xor_sync(0xffffffffu, rm0, 1));
            rm0 = fmaxf(rm0, __shfl_xor_sync(0xffffffffu, rm0, 2));
            rm1 = fmaxf(rm1, __shfl_xor_sync(0xffffffffu, rm1, 1));
            rm1 = fmaxf(rm1, __shfl_xor_sync(0xffffffffu, rm1, 2));

            float mn0 = fmaxf(mr[mt][0], rm0);
            float mn1 = fmaxf(mr[mt][1], rm1);
            float a0 = __expf(mr[mt][0] - mn0);
            float a1 = __expf(mr[mt][1] - mn1);
            mr[mt][0] = mn0; mr[mt][1] = mn1;

            int rb = warp * 32 + mt * 16;
            float ls0 = 0.f, ls1 = 0.f;
#pragma unroll
            for (int nt = 0; nt < 8; nt++) {
                float p00 = __expf(s[mt][nt][0] - mn0);
                float p01 = __expf(s[mt][nt][1] - mn0);
                float p10 = __expf(s[mt][nt][2] - mn1);
                float p11 = __expf(s[mt][nt][3] - mn1);
                ls0 += p00 + p01;
                ls1 += p10 + p11;
                int cb = nt * 8 + 2 * tg;
                *(float2*)&Qs[(rb + g) * LDS_ + cb] =
                    make_float2(f2tf_f(p00), f2tf_f(p01));
                *(float2*)&Qs[(rb + g + 8) * LDS_ + cb] =
                    make_float2(f2tf_f(p10), f2tf_f(p11));
                o[mt][nt][0] *= a0; o[mt][nt][1] *= a0;
                o[mt][nt][2] *= a1; o[mt][nt][3] *= a1;
            }
            ls0 += __shfl_xor_sync(0xffffffffu, ls0, 1);
            ls0 += __shfl_xor_sync(0xffffffffu, ls0, 2);
            ls1 += __shfl_xor_sync(0xffffffffu, ls1, 1);
            ls1 += __shfl_xor_sync(0xffffffffu, ls1, 2);
            lr[mt][0] = lr[mt][0] * a0 + ls0;
            lr[mt][1] = lr[mt][1] * a1 + ls1;
        }
        __syncwarp();   // P visible within warp before LDSM of own rows

        // O += P V
#pragma unroll
        for (int ks = 0; ks < 8; ks++) {
            uint32_t pf[2][4], vf[4][4];
            ldsm_x4(pf[0], aP0 + ks * 32);
            ldsm_x4(pf[1], aP1 + ks * 32);
#pragma unroll
            for (int p = 0; p < 4; p++)
                ldsm_x4(vf[p], bV + p * (16 * LDS_ * 4) + ks * 32);
#pragma unroll
            for (int p = 0; p < 4; p++) {
                mma8(o[0][2 * p],     pf[0], &vf[p][0]);
                mma8(o[0][2 * p + 1], pf[0], &vf[p][2]);
                mma8(o[1][2 * p],     pf[1], &vf[p][0]);
                mma8(o[1][2 * p + 1], pf[1], &vf[p][2]);
            }
        }
    }

    // Normalize and write out (raw fp32; out-GEMM rounds its own inputs)
#pragma unroll
    for (int mt = 0; mt < 2; mt++) {
        float i0 = 1.f / lr[mt][0];
        float i1 = 1.f / lr[mt][1];
        const size_t ob = ((size_t)b * SS + s0 + warp * 32 + mt * 16) * CHN + h * HD;
#pragma unroll
        for (int nt = 0; nt < 8; nt++) {
            int col = nt * 8 + 2 * tg;
            float2 v0 = make_float2(o[mt][nt][0] * i0, o[mt][nt][1] * i0);
            float2 v1 = make_float2(o[mt][nt][2] * i1, o[mt][nt][3] * i1);
            *(float2*)&g_A[ob + (size_t)g * CHN + col] = v0;
            *(float2*)&g_A[ob + (size_t)(g + 8) * CHN + col] = v1;
        }
    }
}

// ---------------- launch ----------------
extern "C" void kernel_launch(void* const* d_in, const int* in_sizes, int n_in,
                              void* d_out, int out_size)
{
    const float* query = (const float*)d_in[0];
    const float* key   = (const float*)d_in[1];
    const float* value = (const float*)d_in[2];
    const float* mask  = (const float*)d_in[3];
    const float* Wq    = (const float*)d_in[4];
    const float* bq    = (const float*)d_in[5];
    const float* Wk    = (const float*)d_in[6];
    const float* bk    = (const float*)d_in[7];
    const float* Wv    = (const float*)d_in[8];
    const float* bv    = (const float*)d_in[9];
    const float* Wo    = (const float*)d_in[10];
    const float* bo    = (const float*)d_in[11];
    const int*   causal = (const int*)d_in[12];
    float* out = (float*)d_out;

    float *Qp, *Kp, *Vp, *Ap;
    cudaGetSymbolAddress((void**)&Qp, g_Q);
    cudaGetSymbolAddress((void**)&Kp, g_K);
    cudaGetSymbolAddress((void**)&Vp, g_V);
    cudaGetSymbolAddress((void**)&Ap, g_A);

    const int gsmem = 2 * GSTGB;   // 73,728 B
    cudaFuncSetAttribute(qkv_gemm_kernel,
                         cudaFuncAttributeMaxDynamicSharedMemorySize, gsmem);
    cudaFuncSetAttribute(out_gemm_kernel,
                         cudaFuncAttributeMaxDynamicSharedMemorySize, gsmem);

    qkv_gemm_kernel<<<dim3(8, 32, 3), 256, gsmem>>>(
        query, key, value, Wq, Wk, Wv, bq, bk, bv, Qp, Kp, Vp);

    const int fsmem = (128 * LDS_ + 4 * KSTG) * (int)sizeof(float);   // 104,448 B
    cudaFuncSetAttribute(flash_attn_kernel,
                         cudaFuncAttributeMaxDynamicSharedMemorySize, fsmem);
    flash_attn_kernel<<<dim3(SS / 128, NH, BB), 128, fsmem>>>(mask, causal);

    out_gemm_kernel<<<dim3(8, 32), 256, gsmem>>>(Ap, Wo, bo, out, mask);
}

// round 15
// speedup vs baseline: 1.0696x; 1.0227x over previous
#include <cuda_runtime.h>
#include <cstdint>

// Problem constants
#define BB   2
#define SS   2048
#define TT   2048
#define CHN  1024
#define NH   16
#define HD   64
#define MM   (BB * SS)   // 4096 rows

// Scratch (device globals: allocation-free rule)
// g_V holds V TRANSPOSED: Vt[((b*NH+h)*HD + d) * TT + t]
// g_Wt holds 4 pre-rounded, pre-transposed weights: Wt_z[n*1024+k] = tf32(W_z[k][n])
__device__ float g_Q[(size_t)MM * CHN];
__device__ float g_K[(size_t)MM * CHN];
__device__ float g_V[(size_t)MM * CHN];
__device__ float g_A[(size_t)MM * CHN];
__device__ float g_Wt[(size_t)4 * CHN * CHN];

// ---------------- helpers ----------------
__device__ __forceinline__ uint32_t f2tf(float x) {
    uint32_t u;
    asm("cvt.rna.tf32.f32 %0, %1;\n" : "=r"(u) : "f"(x));
    return u;
}
__device__ __forceinline__ float f2tf_f(float x) {
    return __uint_as_float(f2tf(x));
}
__device__ __forceinline__ uint32_t fu(float x) { return __float_as_uint(x); }

__device__ __forceinline__ float4 tf4(float4 v) {
    return make_float4(f2tf_f(v.x), f2tf_f(v.y), f2tf_f(v.z), f2tf_f(v.w));
}

__device__ __forceinline__ uint32_t smem_u32(const void* p) {
    return (uint32_t)__cvta_generic_to_shared(p);
}

__device__ __forceinline__ void cpa16(uint32_t dst_smem, const float* src) {
    asm volatile("cp.async.cg.shared.global [%0], [%1], 16;\n"
                 :: "r"(dst_smem), "l"(src));
}
__device__ __forceinline__ void cp_commit() {
    asm volatile("cp.async.commit_group;\n");
}
__device__ __forceinline__ void cp_wait0() {
    asm volatile("cp.async.wait_group 0;\n");
}

// D(16x8) += A(16x8, tf32, row) * B(8x8, tf32, col)
__device__ __forceinline__ void mma8(float c[4], const uint32_t a[4], const uint32_t b[2]) {
    asm volatile(
        "mma.sync.aligned.m16n8k8.row.col.f32.tf32.tf32.f32 "
        "{%0,%1,%2,%3}, {%4,%5,%6,%7}, {%8,%9}, {%0,%1,%2,%3};\n"
        : "+f"(c[0]), "+f"(c[1]), "+f"(c[2]), "+f"(c[3])
        : "r"(a[0]), "r"(a[1]), "r"(a[2]), "r"(a[3]), "r"(b[0]), "r"(b[1]));
}

// ldmatrix x4: 4 8x8-b16 matrices (= 8x4-tf32 blocks); exact tf32 frag layout.
__device__ __forceinline__ void ldsm_x4(uint32_t r[4], uint32_t saddr) {
    asm volatile("ldmatrix.sync.aligned.m8n8.x4.shared.b16 {%0,%1,%2,%3}, [%4];"
        : "=r"(r[0]), "=r"(r[1]), "=r"(r[2]), "=r"(r[3]) : "r"(saddr));
}

// ---------------- weight prep: Wt_z[n][k] = tf32(W_z[k][n]) ----------------
__global__ void wtrans_kernel(
    const float* __restrict__ Wq, const float* __restrict__ Wk,
    const float* __restrict__ Wv, const float* __restrict__ Wo,
    float* __restrict__ Wt)
{
    __shared__ float t[32][33];
    const int z = blockIdx.z;
    const float* W = (z == 0) ? Wq : (z == 1) ? Wk : (z == 2) ? Wv : Wo;
    float* D = Wt + (size_t)z * CHN * CHN;

    const int bx = blockIdx.x * 32;   // n block
    const int by = blockIdx.y * 32;   // k block
    const int tx = threadIdx.x;       // 0..31
    const int ty = threadIdx.y;       // 0..7

#pragma unroll
    for (int i = 0; i < 4; i++)
        t[ty + i * 8][tx] = W[(size_t)(by + ty + i * 8) * CHN + bx + tx];
    __syncthreads();
#pragma unroll
    for (int i = 0; i < 4; i++)
        D[(size_t)(bx + ty + i * 8) * CHN + by + tx] = f2tf_f(t[tx][ty + i * 8]);
}

// ---------------- GEMM body: C[4096,1024] = X @ W + bias ----------------
// BM=128, BN=128, BK=32, 256 threads, LDSM fragments, double-buffered smem.
// W always staged via cp.async from pre-rounded Wt[n][k] (no LDG/cvt/STS).
// X_ASYNC: X also via cp.async (requires pre-rounded X, e.g. g_A from flash).
// OUT_MODE: 0 = plain fp32 + optional maskScale; 1 = tf32-rounded (Q,K);
//           2 = tf32-rounded + transposed V layout Vt[(b*16+h)*64+d][t]
#define GXF   (128 * 36)
#define GWF   (128 * 36)
#define GSTG  (GXF + GWF)
#define GSTGB (GSTG * 4)

template <int OUT_MODE, bool X_ASYNC>
__device__ __forceinline__ void gemm_body(
    const float* __restrict__ X, const float* __restrict__ Wt,
    const float* __restrict__ bias, float* __restrict__ C,
    const float* __restrict__ maskScale, float* gsm)
{
    const uint32_t gsb = smem_u32(gsm);

    const int tid  = threadIdx.x;
    const int lane = tid & 31;
    const int warp = tid >> 5;
    const int g    = lane >> 2;
    const int tg   = lane & 3;
    const int wm   = warp >> 1;   // 0..3
    const int wn   = warp & 1;    // 0..1
    const int m0   = blockIdx.y * 128;
    const int n0   = blockIdx.x * 128;

    const uint32_t a_thr = (uint32_t)(((wm * 32 + (lane & 15)) * 36 + (lane >> 4) * 4) * 4);
    const uint32_t b_thr = (uint32_t)(((wn * 64 + ((lane >> 4) * 8) + (lane & 7)) * 36
                                      + (((lane >> 3) & 1) * 4)) * 4);

    float4 px[4];   // X prefetch (non-async path only)

    auto issue_async = [&](int ktile, int st) {
        const int kt = ktile * 32;
        const uint32_t base = gsb + (uint32_t)(st * GSTGB);
#pragma unroll
        for (int i = 0; i < 4; i++) {
            int idx = i * 256 + tid;
            int r = idx >> 3, cq = (idx & 7) * 4;
            cpa16(base + (uint32_t)(GXF * 4) + (uint32_t)((r * 36 + cq) * 4),
                  &Wt[(size_t)(n0 + r) * 1024 + kt + cq]);
            if (X_ASYNC)
                cpa16(base + (uint32_t)((r * 36 + cq) * 4),
                      &X[(size_t)(m0 + r) * 1024 + kt + cq]);
        }
        cp_commit();
    };
    auto ldg_x = [&](int kt) {
#pragma unroll
        for (int i = 0; i < 4; i++) {
            int idx = i * 256 + tid;
            int xr = idx >> 3, xc = (idx & 7) * 4;
            px[i] = *(const float4*)&X[(size_t)(m0 + xr) * 1024 + kt + xc];
        }
    };
    auto sts_x = [&](int st) {
        float* Xs = gsm + st * GSTG;
#pragma unroll
        for (int i = 0; i < 4; i++) {
            int idx = i * 256 + tid;
            int xr = idx >> 3, xc = (idx & 7) * 4;
            *(float4*)&Xs[xr * 36 + xc] = tf4(px[i]);
        }
    };

    float c[2][8][4];
#pragma unroll
    for (int mt = 0; mt < 2; mt++)
#pragma unroll
        for (int nt = 0; nt < 8; nt++)
#pragma unroll
            for (int e = 0; e < 4; e++) c[mt][nt][e] = 0.f;

    if (!X_ASYNC) ldg_x(0);
    issue_async(0, 0);
    if (!X_ASYNC) sts_x(0);
    cp_wait0();
    __syncthreads();

    for (int kt = 0; kt < 32; kt++) {
        const int st = kt & 1;
        if (kt + 1 < 32) {
            if (!X_ASYNC) ldg_x((kt + 1) * 32);
            issue_async(kt + 1, st ^ 1);   // overlaps compute below
        }

        const uint32_t xa = gsb + (uint32_t)(st * GSTGB) + a_thr;
        const uint32_t wa = gsb + (uint32_t)(st * GSTGB) + (uint32_t)(GXF * 4) + b_thr;

#pragma unroll
        for (int kk = 0; kk < 4; kk++) {
            uint32_t af[2][4], bf[4][4];
            ldsm_x4(af[0], xa + kk * 32);
            ldsm_x4(af[1], xa + 16 * 36 * 4 + kk * 32);
#pragma unroll
            for (int p = 0; p < 4; p++)
                ldsm_x4(bf[p], wa + p * (16 * 36 * 4) + kk * 32);
#pragma unroll
            for (int p = 0; p < 4; p++) {
                mma8(c[0][2 * p],     af[0], &bf[p][0]);
                mma8(c[0][2 * p + 1], af[0], &bf[p][2]);
                mma8(c[1][2 * p],     af[1], &bf[p][0]);
                mma8(c[1][2 * p + 1], af[1], &bf[p][2]);
            }
        }

        if (kt + 1 < 32) {
            if (!X_ASYNC) sts_x(st ^ 1);
            cp_wait0();
            __syncthreads();
        }
    }

#pragma unroll
    for (int mt = 0; mt < 2; mt++) {
        int r0 = m0 + wm * 32 + mt * 16 + g;
        int r1 = r0 + 8;
        if (OUT_MODE == 2) {
            // Transposed V store: Vt[(b*16+h)*64+d][t]; whole CTA is one b.
            const size_t bbase = (size_t)(r0 >> 11) * NH * HD;   // b * 1024
            const int t0v = r0 & 2047, t1v = r1 & 2047;
#pragma unroll
            for (int nt = 0; nt < 8; nt++) {
                int col = n0 + wn * 64 + nt * 8 + 2 * tg;
                float b0 = bias[col], b1 = bias[col + 1];
                const size_t vr0 = (bbase + col) * TT;
                const size_t vr1 = vr0 + TT;
                C[vr0 + t0v] = f2tf_f(c[mt][nt][0] + b0);
                C[vr1 + t0v] = f2tf_f(c[mt][nt][1] + b1);
                C[vr0 + t1v] = f2tf_f(c[mt][nt][2] + b0);
                C[vr1 + t1v] = f2tf_f(c[mt][nt][3] + b1);
            }
        } else {
            float sc0 = 1.f, sc1 = 1.f;
            if (OUT_MODE == 0 && maskScale) {
                sc0 = maskScale[(size_t)r0 * TT];
                sc1 = maskScale[(size_t)r1 * TT];
            }
#pragma unroll
            for (int nt = 0; nt < 8; nt++) {
                int col = n0 + wn * 64 + nt * 8 + 2 * tg;
                float b0 = bias[col], b1 = bias[col + 1];
                float v00 = (c[mt][nt][0] + b0) * sc0;
                float v01 = (c[mt][nt][1] + b1) * sc0;
                float v10 = (c[mt][nt][2] + b0) * sc1;
                float v11 = (c[mt][nt][3] + b1) * sc1;
                if (OUT_MODE == 1) {
                    v00 = f2tf_f(v00); v01 = f2tf_f(v01);
                    v10 = f2tf_f(v10); v11 = f2tf_f(v11);
                }
                *(float2*)&C[(size_t)r0 * 1024 + col] = make_float2(v00, v01);
                *(float2*)&C[(size_t)r1 * 1024 + col] = make_float2(v10, v11);
            }
        }
    }
}

// Fused QKV projections: blockIdx.z picks (input, Wt slice, bias, output)
__global__ void __launch_bounds__(256, 2) qkv_gemm_kernel(
    const float* __restrict__ query, const float* __restrict__ key,
    const float* __restrict__ value,
    const float* __restrict__ Wt,
    const float* __restrict__ bq, const float* __restrict__ bk,
    const float* __restrict__ bv,
    float* __restrict__ Qp, float* __restrict__ Kp, float* __restrict__ Vp)
{
    extern __shared__ float gsm[];
    const int z = blockIdx.z;   // uniform per CTA
    const float* Wz = Wt + (size_t)z * CHN * CHN;
    if (z == 0)      gemm_body<1, false>(query, Wz, bq, Qp, nullptr, gsm);
    else if (z == 1) gemm_body<1, false>(key,   Wz, bk, Kp, nullptr, gsm);
    else             gemm_body<2, false>(value, Wz, bv, Vp, nullptr, gsm);
}

// Output projection: X = g_A (pre-rounded by flash) -> fully async staging.
__global__ void __launch_bounds__(256, 2) out_gemm_kernel(
    const float* __restrict__ X, const float* __restrict__ Wt,
    const float* __restrict__ bias, float* __restrict__ C,
    const float* __restrict__ maskScale)
{
    extern __shared__ float gsm[];
    gemm_body<0, true>(X, Wt + (size_t)3 * CHN * CHN, bias, C, maskScale, gsm);
}

// ---------------- Flash attention (R14-proven) + pre-rounded g_A epilogue ----
#define LDS_  68
#define FCH   64
#define NCH   (TT / FCH)
#define KSTG  (64 * LDS_)   // floats per K or V stage

__global__ void __launch_bounds__(128) flash_attn_kernel(
    const float* __restrict__ mask, const int* __restrict__ causal_p)
{
    extern __shared__ float sm[];
    float* Qs = sm;                            // 128 x 68 (P reuses own rows)
    float* Ks = sm + 128 * LDS_;               // 2 stages x 64 x 68  [t][d]
    float* Vs = sm + 128 * LDS_ + 2 * KSTG;    // 2 stages x 64 x 68  [d][t]

    const int tid  = threadIdx.x;
    const int lane = tid & 31;
    const int warp = tid >> 5;
    const int g    = lane >> 2;
    const int tg   = lane & 3;
    const int s0   = blockIdx.x * 128;
    const int h    = blockIdx.y;
    const int b    = blockIdx.z;
    const int causal = causal_p[0];

    const uint32_t Qs_u = smem_u32(Qs);
    const uint32_t Ks_u = smem_u32(Ks);
    const uint32_t Vs_u = smem_u32(Vs);

    const uint32_t bKthr = (uint32_t)(((((lane >> 4) * 8) + (lane & 7)) * LDS_
                                       + (((lane >> 3) & 1) * 4)) * 4);
    const uint32_t bVthr = bKthr;
    const uint32_t aP0 = Qs_u + (uint32_t)(((warp * 32 + (lane & 15)) * LDS_
                                            + ((lane >> 4) * 4)) * 4);
    const uint32_t aP1 = aP0 + (uint32_t)(16 * LDS_ * 4);

    auto issue_kv = [&](int ic, int st) {
        const size_t koff = ((size_t)b * TT + ic * FCH) * CHN + h * HD;
        const uint32_t kb = Ks_u + (uint32_t)(st * KSTG * 4);
#pragma unroll
        for (int i = 0; i < 8; i++) {
            int idx = i * 128 + tid;
            int r = idx >> 4, cc = (idx & 15) * 4;
            cpa16(kb + (uint32_t)((r * LDS_ + cc) * 4),
                  &g_K[koff + (size_t)r * CHN + cc]);
        }
        const size_t voff = (((size_t)b * NH + h) * HD) * TT + ic * FCH;
        const uint32_t vb = Vs_u + (uint32_t)(st * KSTG * 4);
#pragma unroll
        for (int i = 0; i < 8; i++) {
            int idx = i * 128 + tid;
            int d = idx >> 4, q = (idx & 15) * 4;
            cpa16(vb + (uint32_t)((d * LDS_ + q) * 4),
                  &g_V[voff + (size_t)d * TT + q]);
        }
        cp_commit();
    };

    const size_t qoff = ((size_t)b * SS + s0) * CHN + h * HD;
#pragma unroll
    for (int i = 0; i < 16; i++) {
        int idx = i * 128 + tid;
        int r = idx >> 4, cc = (idx & 15) * 4;
        *(float4*)&Qs[r * LDS_ + cc] = *(const float4*)&g_Q[qoff + (size_t)r * CHN + cc];
    }
    issue_kv(0, 0);
    __syncthreads();

    uint32_t qa[2][8][4];
#pragma unroll
    for (int mt = 0; mt < 2; mt++) {
        uint32_t base = (mt == 0) ? aP0 : aP1;
#pragma unroll
        for (int j = 0; j < 8; j++) ldsm_x4(qa[mt][j], base + j * 32);
    }

    float o[2][8][4];
#pragma unroll
    for (int mt = 0; mt < 2; mt++)
#pragma unroll
        for (int nt = 0; nt < 8; nt++)
#pragma unroll
            for (int e = 0; e < 4; e++) o[mt][nt][e] = 0.f;
    float mr[2][2] = {{-1e30f, -1e30f}, {-1e30f, -1e30f}};
    float lr[2][2] = {{0.f, 0.f}, {0.f, 0.f}};

    const float* mb = mask + (size_t)b * SS * TT;

    for (int ic = 0; ic < NCH; ic++) {
        const int t0 = ic * FCH;
        const int st = ic & 1;

        cp_wait0();
        __syncthreads();
        if (ic + 1 < NCH) issue_kv(ic + 1, st ^ 1);

        const uint32_t bK = Ks_u + (uint32_t)(st * KSTG * 4) + bKthr;
        const uint32_t bV = Vs_u + (uint32_t)(st * KSTG * 4) + bVthr;

        float s[2][8][4];
#pragma unroll
        for (int mt = 0; mt < 2; mt++)
#pragma unroll
            for (int nt = 0; nt < 8; nt++)
#pragma unroll
                for (int e = 0; e < 4; e++) s[mt][nt][e] = 0.f;
#pragma unroll
        for (int ks = 0; ks < 8; ks++) {
            uint32_t kf[4][4];
#pragma unroll
            for (int p = 0; p < 4; p++)
                ldsm_x4(kf[p], bK + p * (16 * LDS_ * 4) + ks * 32);
#pragma unroll
            for (int p = 0; p < 4; p++) {
                mma8(s[0][2 * p],     qa[0][ks], &kf[p][0]);
                mma8(s[0][2 * p + 1], qa[0][ks], &kf[p][2]);
                mma8(s[1][2 * p],     qa[1][ks], &kf[p][0]);
                mma8(s[1][2 * p + 1], qa[1][ks], &kf[p][2]);
            }
        }

        if (!causal) {
            bool mz[8][2];
#pragma unroll
            for (int nt = 0; nt < 8; nt++)
#pragma unroll
                for (int e = 0; e < 2; e++)
                    mz[nt][e] = (mb[t0 + nt * 8 + 2 * tg + e] == 0.f);
#pragma unroll
            for (int mt = 0; mt < 2; mt++)
#pragma unroll
                for (int nt = 0; nt < 8; nt++)
#pragma unroll
                    for (int e = 0; e < 2; e++) {
                        s[mt][nt][e]     = mz[nt][e] ? -1e30f : s[mt][nt][e] * 0.125f;
                        s[mt][nt][2 + e] = mz[nt][e] ? -1e30f : s[mt][nt][2 + e] * 0.125f;
                    }
        } else {
#pragma unroll
            for (int mt = 0; mt < 2; mt++) {
                int rg0 = s0 + warp * 32 + mt * 16 + g;
                int rg1 = rg0 + 8;
#pragma unroll
                for (int nt = 0; nt < 8; nt++) {
#pragma unroll
                    for (int e = 0; e < 2; e++) {
                        int t = t0 + nt * 8 + 2 * tg + e;
                        float v0 = s[mt][nt][e] * 0.125f;
                        float v1 = s[mt][nt][2 + e] * 0.125f;
                        if (mb[(size_t)rg0 * TT + t] == 0.f && t <= rg0) v0 = -1e30f;
                        if (mb[(size_t)rg1 * TT + t] == 0.f && t <= rg1) v1 = -1e30f;
                        s[mt][nt][e] = v0;
                        s[mt][nt][2 + e] = v1;
                    }
                }
            }
        }

#pragma unroll
        for (int mt = 0; mt < 2; mt++) {
            float rm0 = -1e30f, rm1 = -1e30f;
#pragma unroll
            for (int nt = 0; nt < 8; nt++) {
                rm0 = fmaxf(rm0, fmaxf(s[mt][nt][0], s[mt][nt][1]));
                rm1 = fmaxf(rm1, fmaxf(s[mt][nt][2], s[mt][nt][3]));
            }
            rm0 = fmaxf(rm0, __shfl_xor_sync(0xffffffffu, rm0, 1));
            rm0 = fmaxf(rm0, __shfl_xor_sync(0xffffffffu, rm0, 2));
            rm1 = fmaxf(rm1, __shfl_xor_sync(0xffffffffu, rm1, 1));
            rm1 = fmaxf(rm1, __shfl_xor_sync(0xffffffffu, rm1, 2));

            float mn0 = fmaxf(mr[mt][0], rm0);
            float mn1 = fmaxf(mr[mt][1], rm1);
            float a0 = __expf(mr[mt][0] - mn0);
            float a1 = __expf(mr[mt][1] - mn1);
            mr[mt][0] = mn0; mr[mt][1] = mn1;

            int rb = warp * 32 + mt * 16;
            float ls0 = 0.f, ls1 = 0.f;
#pragma unroll
            for (int nt = 0; nt < 8; nt++) {
                float p00 = __expf(s[mt][nt][0] - mn0);
                float p01 = __expf(s[mt][nt][1] - mn0);
                float p10 = __expf(s[mt][nt][2] - mn1);
                float p11 = __expf(s[mt][nt][3] - mn1);
                ls0 += p00 + p01;
                ls1 += p10 + p11;
                int cb = nt * 8 + 2 * tg;
                *(float2*)&Qs[(rb + g) * LDS_ + cb] =
                    make_float2(f2tf_f(p00), f2tf_f(p01));
                *(float2*)&Qs[(rb + g + 8) * LDS_ + cb] =
                    make_float2(f2tf_f(p10), f2tf_f(p11));
                o[mt][nt][0] *= a0; o[mt][nt][1] *= a0;
                o[mt][nt][2] *= a1; o[mt][nt][3] *= a1;
            }
            ls0 += __shfl_xor_sync(0xffffffffu, ls0, 1);
            ls0 += __shfl_xor_sync(0xffffffffu, ls0, 2);
            ls1 += __shfl_xor_sync(0xffffffffu, ls1, 1);
            ls1 += __shfl_xor_sync(0xffffffffu, ls1, 2);
            lr[mt][0] = lr[mt][0] * a0 + ls0;
            lr[mt][1] = lr[mt][1] * a1 + ls1;
        }
        __syncwarp();

#pragma unroll
        for (int ks = 0; ks < 8; ks++) {
            uint32_t pf[2][4], vf[4][4];
            ldsm_x4(pf[0], aP0 + ks * 32);
            ldsm_x4(pf[1], aP1 + ks * 32);
#pragma unroll
            for (int p = 0; p < 4; p++)
                ldsm_x4(vf[p], bV + p * (16 * LDS_ * 4) + ks * 32);
#pragma unroll
            for (int p = 0; p < 4; p++) {
                mma8(o[0][2 * p],     pf[0], &vf[p][0]);
                mma8(o[0][2 * p + 1], pf[0], &vf[p][2]);
                mma8(o[1][2 * p],     pf[1], &vf[p][0]);
                mma8(o[1][2 * p + 1], pf[1], &vf[p][2]);
            }
        }
    }

    // Normalize and write out PRE-ROUNDED to tf32 (out-GEMM stages g_A raw
    // via cp.async; f2tf idempotent -> final result bit-identical).
#pragma unroll
    for (int mt = 0; mt < 2; mt++) {
        float i0 = 1.f / lr[mt][0];
        float i1 = 1.f / lr[mt][1];
        const size_t ob = ((size_t)b * SS + s0 + warp * 32 + mt * 16) * CHN + h * HD;
#pragma unroll
        for (int nt = 0; nt < 8; nt++) {
            int col = nt * 8 + 2 * tg;
            float2 v0 = make_float2(f2tf_f(o[mt][nt][0] * i0), f2tf_f(o[mt][nt][1] * i0));
            float2 v1 = make_float2(f2tf_f(o[mt][nt][2] * i1), f2tf_f(o[mt][nt][3] * i1));
            *(float2*)&g_A[ob + (size_t)g * CHN + col] = v0;
            *(float2*)&g_A[ob + (size_t)(g + 8) * CHN + col] = v1;
        }
    }
}

// ---------------- launch ----------------
extern "C" void kernel_launch(void* const* d_in, const int* in_sizes, int n_in,
                              void* d_out, int out_size)
{
    const float* query = (const float*)d_in[0];
    const float* key   = (const float*)d_in[1];
    const float* value = (const float*)d_in[2];
    const float* mask  = (const float*)d_in[3];
    const float* Wq    = (const float*)d_in[4];
    const float* bq    = (const float*)d_in[5];
    const float* Wk    = (const float*)d_in[6];
    const float* bk    = (const float*)d_in[7];
    const float* Wv    = (const float*)d_in[8];
    const float* bv    = (const float*)d_in[9];
    const float* Wo    = (const float*)d_in[10];
    const float* bo    = (const float*)d_in[11];
    const int*   causal = (const int*)d_in[12];
    float* out = (float*)d_out;

    float *Qp, *Kp, *Vp, *Ap, *Wtp;
    cudaGetSymbolAddress((void**)&Qp, g_Q);
    cudaGetSymbolAddress((void**)&Kp, g_K);
    cudaGetSymbolAddress((void**)&Vp, g_V);
    cudaGetSymbolAddress((void**)&Ap, g_A);
    cudaGetSymbolAddress((void**)&Wtp, g_Wt);

    // One-time weight prep: pre-round + pre-transpose all 4 weights
    wtrans_kernel<<<dim3(32, 32, 4), dim3(32, 8)>>>(Wq, Wk, Wv, Wo, Wtp);

    const int gsmem = 2 * GSTGB;   // 73,728 B
    cudaFuncSetAttribute(qkv_gemm_kernel,
                         cudaFuncAttributeMaxDynamicSharedMemorySize, gsmem);
    cudaFuncSetAttribute(out_gemm_kernel,
                         cudaFuncAttributeMaxDynamicSharedMemorySize, gsmem);

    qkv_gemm_kernel<<<dim3(8, 32, 3), 256, gsmem>>>(
        query, key, value, Wtp, bq, bk, bv, Qp, Kp, Vp);

    const int fsmem = (128 * LDS_ + 4 * KSTG) * (int)sizeof(float);   // 104,448 B
    cudaFuncSetAttribute(flash_attn_kernel,
                         cudaFuncAttributeMaxDynamicSharedMemorySize, fsmem);
    flash_attn_kernel<<<dim3(SS / 128, NH, BB), 128, fsmem>>>(mask, causal);

    out_gemm_kernel<<<dim3(8, 32), 256, gsmem>>>(Ap, Wtp, bo, out, mask);
}